// round 6
// baseline (speedup 1.0000x reference)
#include <cuda_runtime.h>
#include <cuda_bf16.h>
#include <cstdint>

// ---------------------------------------------------------------------------
// Shapes: B=2, C=256, Im 768x1280, strides {4,8,16,32}, N=1024 rois
// pool5 D = 256*49 = 12544; fc1: 12544->1024 relu; fc2: 1024->1024 relu; proj->20
// ---------------------------------------------------------------------------

#define NCH 256

// tcgen05 is arch-specific (sm_103a); gate so the baseline compute_103 ptxas
// pass compiles a SIMT fallback instead (driver picks the 103a cubin at run).
#if defined(__CUDA_ARCH__) && defined(__CUDA_ARCH_FEAT_SM103_ALL)
#define HAS_TCGEN05 1
#else
#define HAS_TCGEN05 0
#endif

__device__ float g_nhwc[41779200];
__device__ __nv_bfloat16 g_p5_hi[1024 * 12544];
__device__ __nv_bfloat16 g_p5_lo[1024 * 12544];
__device__ __nv_bfloat16 g_w1_hi[1024 * 12544];
__device__ __nv_bfloat16 g_w1_lo[1024 * 12544];
__device__ __nv_bfloat16 g_fc1_hi[1024 * 1024];
__device__ __nv_bfloat16 g_fc1_lo[1024 * 1024];
__device__ __nv_bfloat16 g_w2_hi[1024 * 1024];
__device__ __nv_bfloat16 g_w2_lo[1024 * 1024];
__device__ float g_fc2[1024 * 1024];

__constant__ size_t c_lvl_off[4] = {0, 31457280, 39321600, 41287680};

// ============================ PTX helpers ==================================
__device__ __forceinline__ uint32_t smem_u32(const void* p) {
    uint32_t a;
    asm("{ .reg .u64 t; cvta.to.shared.u64 t, %1; cvt.u32.u64 %0, t; }" : "=r"(a) : "l"(p));
    return a;
}
__device__ __forceinline__ uint32_t elect_one() {
    uint32_t p;
    asm volatile("{\n\t.reg .pred p;\n\telect.sync _|p, 0xFFFFFFFF;\n\tselp.b32 %0, 1, 0, p;\n\t}" : "=r"(p));
    return p;
}
#define MBARRIER_INIT(addr, cnt) \
    asm volatile("mbarrier.init.shared.b64 [%0], %1;" :: "r"(addr), "r"(cnt) : "memory")
#define MBARRIER_WAIT_PARITY(addr, par) do {                                          \
    uint32_t _m = (addr); uint32_t _p = (par); uint32_t _d;                           \
    asm volatile("{\n\t.reg .pred p;\n\t"                                             \
        "mbarrier.try_wait.parity.acquire.cta.shared::cta.b64 p, [%1], %2;\n\t"       \
        "selp.b32 %0, 1, 0, p;\n\t}" : "=r"(_d) : "r"(_m), "r"(_p) : "memory");       \
    if (!_d) {                                                                        \
        asm volatile("{\n\t.reg .pred P1;\n\t"                                        \
            "WL_%=:\n\t"                                                              \
            "mbarrier.try_wait.parity.acquire.cta.shared::cta.b64 P1, [%0], %1, 0x989680;\n\t" \
            "@P1 bra.uni WD_%=;\n\tbra.uni WL_%=;\n\tWD_%=:\n\t}"                     \
            :: "r"(_m), "r"(_p) : "memory");                                          \
    } } while (0)
#define FENCE_PROXY_ASYNC() asm volatile("fence.proxy.async.shared::cta;" ::: "memory")
#define CP_COMMIT() asm volatile("cp.async.commit_group;" ::: "memory")
#define CP_WAIT_1() asm volatile("cp.async.wait_group 1;" ::: "memory")

#if HAS_TCGEN05
#define TCGEN05_ALLOC(sa, n) \
    asm volatile("tcgen05.alloc.cta_group::1.sync.aligned.shared::cta.b32 [%0], %1;" :: "r"(sa), "r"(n) : "memory")
#define TCGEN05_DEALLOC(t, n) \
    asm volatile("tcgen05.dealloc.cta_group::1.sync.aligned.b32 %0, %1;" :: "r"(t), "r"(n))
#define TCGEN05_RELINQ() \
    asm volatile("tcgen05.relinquish_alloc_permit.cta_group::1.sync.aligned;")
#define TCGEN05_COMMIT(mb) \
    asm volatile("tcgen05.commit.cta_group::1.mbarrier::arrive::one.shared::cluster.b64 [%0];" :: "r"(mb) : "memory")
#define TCGEN05_FENCE_AFTER()  asm volatile("tcgen05.fence::after_thread_sync;" ::: "memory")
#define TCGEN05_FENCE_BEFORE() asm volatile("tcgen05.fence::before_thread_sync;" ::: "memory")
#define TCGEN05_WAIT_LD() asm volatile("tcgen05.wait::ld.sync.aligned;" ::: "memory")

#define TCGEN05_LD_X32(r, ta)                                                          \
    asm volatile("tcgen05.ld.sync.aligned.32x32b.x32.b32 "                             \
        "{%0, %1, %2, %3, %4, %5, %6, %7, %8, %9, %10, %11, %12, %13, %14, %15, "      \
        " %16, %17, %18, %19, %20, %21, %22, %23, %24, %25, %26, %27, %28, %29, %30, %31}, [%32];" \
        : "=r"((r)[0]), "=r"((r)[1]), "=r"((r)[2]), "=r"((r)[3]),                      \
          "=r"((r)[4]), "=r"((r)[5]), "=r"((r)[6]), "=r"((r)[7]),                      \
          "=r"((r)[8]), "=r"((r)[9]), "=r"((r)[10]), "=r"((r)[11]),                    \
          "=r"((r)[12]), "=r"((r)[13]), "=r"((r)[14]), "=r"((r)[15]),                  \
          "=r"((r)[16]), "=r"((r)[17]), "=r"((r)[18]), "=r"((r)[19]),                  \
          "=r"((r)[20]), "=r"((r)[21]), "=r"((r)[22]), "=r"((r)[23]),                  \
          "=r"((r)[24]), "=r"((r)[25]), "=r"((r)[26]), "=r"((r)[27]),                  \
          "=r"((r)[28]), "=r"((r)[29]), "=r"((r)[30]), "=r"((r)[31])                   \
        : "r"(ta))

__device__ __forceinline__ void mma_f16_ss(uint32_t d, uint64_t a, uint64_t b,
                                           uint32_t idesc, bool en) {
    uint32_t e = en ? 1u : 0u;
    asm volatile(
        "{\n\t.reg .pred p;\n\tsetp.ne.u32 p, %4, 0;\n\t"
        "tcgen05.mma.cta_group::1.kind::f16 [%0], %1, %2, %3, {%5, %5, %5, %5}, p;\n\t}"
        :: "r"(d), "l"(a), "l"(b), "r"(idesc), "r"(e), "r"(0u) : "memory");
}
#endif  // HAS_TCGEN05

// SW128 K-major descriptor: layout=2, version=1, SBO=64, LBO=1
static constexpr uint64_t DESC_BASE_SW128 =
    (uint64_t(2) << 61) | (uint64_t(1) << 46) | (uint64_t(64) << 32) | (uint64_t(1) << 16);
#define MAKE_DESC(a) (DESC_BASE_SW128 | ((uint64_t)((a) >> 4) & 0x3FFF))

// idesc kind::f16: F32 accum, BF16 a/b, M=128, N=128
static constexpr uint32_t GEMM_IDESC =
    (1u << 4) | (1u << 7) | (1u << 10) | ((128u / 8u) << 17) | ((128u / 16u) << 24);

__device__ __forceinline__ void pack_hi_lo(float v0, float v1, uint32_t& h, uint32_t& l) {
    asm("cvt.rn.bf16x2.f32 %0, %1, %2;" : "=r"(h) : "f"(v1), "f"(v0));
    float l0 = v0 - __uint_as_float(h << 16);
    float l1 = v1 - __uint_as_float(h & 0xffff0000u);
    asm("cvt.rn.bf16x2.f32 %0, %1, %2;" : "=r"(l) : "f"(l1), "f"(l0));
}

// ---------------------------------------------------------------------------
// NCHW -> NHWC transpose, float4 both sides, up to 4 tiles (32C x 32HW)/block.
// Uniform tail guard: hw0 >= HW -> break (fm3 has HW=960, not /128).
// ---------------------------------------------------------------------------
__global__ void nchw2nhwc_kernel(const float* __restrict__ in, int HW, size_t off) {
    __shared__ float tile[32][33];
    int b = blockIdx.z;
    int c0 = blockIdx.y * 32;
    int t = threadIdx.x;            // 256
    int cr  = t >> 3;               // 0..31
    int f4  = t & 7;                // 0..7

#pragma unroll
    for (int rep = 0; rep < 4; rep++) {
        int hw0 = (blockIdx.x * 4 + rep) * 32;
        if (hw0 >= HW) break;       // uniform across block

        float4 v = *((const float4*)(in + ((size_t)b * NCH + c0 + cr) * HW + hw0) + f4);
        tile[f4 * 4 + 0][cr] = v.x;
        tile[f4 * 4 + 1][cr] = v.y;
        tile[f4 * 4 + 2][cr] = v.z;
        tile[f4 * 4 + 3][cr] = v.w;
        __syncthreads();

        float4 o;
        o.x = tile[cr][f4 * 4 + 0];
        o.y = tile[cr][f4 * 4 + 1];
        o.z = tile[cr][f4 * 4 + 2];
        o.w = tile[cr][f4 * 4 + 3];
        *((float4*)(g_nhwc + off + ((size_t)b * HW + hw0 + cr) * NCH + c0) + f4) = o;
        __syncthreads();
    }
}

// ---------------------------------------------------------------------------
// ROIAlign: one block per roi, 256 threads = channels; writes hi/lo bf16 rows.
// ---------------------------------------------------------------------------
__global__ void roi_align_kernel(const float* __restrict__ rois) {
    extern __shared__ float shbuf[];  // 12544 floats
    __shared__ int   s_ix0[14], s_ix1[14], s_iy0[14], s_iy1[14];
    __shared__ float s_wx0[14], s_wx1[14], s_wy0[14], s_wy1[14];

    int n = blockIdx.x;
    int tid = threadIdx.x;

    const float* r = rois + (size_t)n * 5;
    int   b  = (int)r[0];
    float x1 = r[1], y1 = r[2], x2 = r[3], y2 = r[4];

    float w = x2 - x1, h = y2 - y1;
    float kf = floorf(4.0f + log2f(sqrtf(fmaxf(w * h, 1e-6f)) / 224.0f));
    kf = fminf(fmaxf(kf, 2.0f), 5.0f);
    int lvl = (int)kf - 2;

    float stride = (float)(4 << lvl);
    int H = 768 >> (lvl + 2);
    int W = 1280 >> (lvl + 2);
    const float* base = g_nhwc + c_lvl_off[lvl] + ((size_t)b * H * W) * NCH;

    if (tid < 28) {
        bool isx = tid < 14;
        int  s   = isx ? tid : tid - 14;
        float lo = isx ? x1 : y1;
        float hi = isx ? x2 : y2;
        int size = isx ? W : H;
        float a = lo / stride - 0.5f;
        float bb = hi / stride - 0.5f;
        float coord = a + (bb - a) * (((float)s + 0.5f) / 14.0f);
        float valid = (coord > -1.0f && coord < (float)size) ? 1.0f : 0.0f;
        float cc = fminf(fmaxf(coord, 0.0f), (float)(size - 1));
        int i0 = (int)floorf(cc);
        int i1 = min(i0 + 1, size - 1);
        float frac = cc - (float)i0;
        if (isx) { s_ix0[s] = i0; s_ix1[s] = i1; s_wx0[s] = (1.0f - frac) * valid; s_wx1[s] = frac * valid; }
        else     { s_iy0[s] = i0; s_iy1[s] = i1; s_wy0[s] = (1.0f - frac) * valid; s_wy1[s] = frac * valid; }
    }
    __syncthreads();

    const float* bc = base + tid;
    for (int by = 0; by < 7; by++) {
        float acc[7];
#pragma unroll
        for (int i = 0; i < 2; i++) {
            int sy = by * 2 + i;
            float wy0 = s_wy0[sy], wy1 = s_wy1[sy];
            int row0 = s_iy0[sy] * W;
            int row1 = s_iy1[sy] * W;
#pragma unroll
            for (int bx = 0; bx < 7; bx++) {
                float a = 0.0f;
#pragma unroll
                for (int j = 0; j < 2; j++) {
                    int sx = bx * 2 + j;
                    float wx0 = s_wx0[sx], wx1 = s_wx1[sx];
                    int xa = s_ix0[sx], xb = s_ix1[sx];
                    float v00 = __ldg(bc + (size_t)(row0 + xa) * NCH);
                    float v01 = __ldg(bc + (size_t)(row0 + xb) * NCH);
                    float v10 = __ldg(bc + (size_t)(row1 + xa) * NCH);
                    float v11 = __ldg(bc + (size_t)(row1 + xb) * NCH);
                    a += wy0 * (wx0 * v00 + wx1 * v01) + wy1 * (wx0 * v10 + wx1 * v11);
                }
                acc[bx] = (i == 0) ? a : acc[bx] + a;
            }
        }
#pragma unroll
        for (int bx = 0; bx < 7; bx++)
            shbuf[tid * 49 + by * 7 + bx] = acc[bx] * 0.25f;
    }
    __syncthreads();

    uint32_t* hd = (uint32_t*)(g_p5_hi + (size_t)n * 12544);
    uint32_t* ld = (uint32_t*)(g_p5_lo + (size_t)n * 12544);
    for (int i = tid; i < 6272; i += 256) {
        float v0 = shbuf[2 * i], v1 = shbuf[2 * i + 1];
        uint32_t hh, ll;
        pack_hi_lo(v0, v1, hh, ll);
        hd[i] = hh; ld[i] = ll;
    }
}

// ---------------------------------------------------------------------------
// fp32 -> bf16 hi/lo split (for weights)
// ---------------------------------------------------------------------------
__global__ void split_kernel(const float* __restrict__ in,
                             __nv_bfloat16* __restrict__ hi,
                             __nv_bfloat16* __restrict__ lo, int n4) {
    int i = blockIdx.x * blockDim.x + threadIdx.x;
    if (i >= n4) return;
    float4 v = ((const float4*)in)[i];
    uint32_t h0, h1, l0, l1;
    pack_hi_lo(v.x, v.y, h0, l0);
    pack_hi_lo(v.z, v.w, h1, l1);
    ((uint2*)hi)[i] = make_uint2(h0, h1);
    ((uint2*)lo)[i] = make_uint2(l0, l1);
}

// ---------------------------------------------------------------------------
// GEMM: C[M,N] = A[M,K] @ B[N,K]^T + bias, ReLU.
// sm_103a: tcgen05, D = Ah*Bh + Ah*Bl + Al*Bh, fp32 TMEM accumulation.
// 128x128 tile, BK=64, 256 threads, cp.async 3-stage pipeline with lagged
// MMA-completion wait.
// ---------------------------------------------------------------------------
__device__ __forceinline__ void load_tile16(uint32_t s_tile, const __nv_bfloat16* g,
                                            int ldK, int tid) {
#pragma unroll
    for (int q = 0; q < 4; q++) {
        int gid = tid + q * 256;
        int row = gid >> 3, c16 = gid & 7;
        uint32_t dst = s_tile + row * 128 + ((c16 ^ (row & 7)) << 4);
        const char* src = (const char*)(g + (size_t)row * ldK) + (c16 << 4);
        asm volatile("cp.async.cg.shared.global [%0], [%1], 16;" :: "r"(dst), "l"(src) : "memory");
    }
}

template <bool SPLIT_OUT>
__global__ __launch_bounds__(256, 1) void gemm_tc(
    const __nv_bfloat16* __restrict__ Ahi, const __nv_bfloat16* __restrict__ Alo,
    const __nv_bfloat16* __restrict__ Bhi, const __nv_bfloat16* __restrict__ Blo,
    const float* __restrict__ bias,
    float* __restrict__ Cf, __nv_bfloat16* __restrict__ Chi, __nv_bfloat16* __restrict__ Clo,
    int N, int K) {
    extern __shared__ char dsm[];
    int tid = threadIdx.x;
    int bm = blockIdx.y * 128, bn = blockIdx.x * 128;

#if HAS_TCGEN05
    __shared__ uint32_t s_tmem;
    __shared__ uint64_t s_mbar[3];

    uint32_t sbase = (smem_u32(dsm) + 1023u) & ~1023u;
    int wid = tid >> 5, lid = tid & 31;

    uint32_t mb[3] = { smem_u32(&s_mbar[0]), smem_u32(&s_mbar[1]), smem_u32(&s_mbar[2]) };

    if (wid == 0) TCGEN05_ALLOC(smem_u32(&s_tmem), 128);
    if (tid == 0) { MBARRIER_INIT(mb[0], 1); MBARRIER_INIT(mb[1], 1); MBARRIER_INIT(mb[2], 1); }
    __syncthreads();
    uint32_t tmem = s_tmem;
    if (wid == 0) TCGEN05_RELINQ();

    const int nblk = K >> 6;

    const __nv_bfloat16* Ah = Ahi + (size_t)bm * K;
    const __nv_bfloat16* Al = Alo + (size_t)bm * K;
    const __nv_bfloat16* Bh = Bhi + (size_t)bn * K;
    const __nv_bfloat16* Bl = Blo + (size_t)bn * K;

#pragma unroll
    for (int p = 0; p < 2; p++) {
        uint32_t st = sbase + (uint32_t)p * 65536u;
        load_tile16(st,          Ah + p * 64, K, tid);
        load_tile16(st + 16384u, Al + p * 64, K, tid);
        load_tile16(st + 32768u, Bh + p * 64, K, tid);
        load_tile16(st + 49152u, Bl + p * 64, K, tid);
        CP_COMMIT();
    }

    int ph[3] = {0, 0, 0};
    int s = 0, sp = 2;
    for (int i = 0; i < nblk; i++) {
        CP_WAIT_1();
        __syncthreads();
        if (tid < 32) {
            if (elect_one()) {
                FENCE_PROXY_ASYNC();
                uint32_t st = sbase + (uint32_t)s * 65536u;
                uint64_t dah = MAKE_DESC(st);
                uint64_t dal = MAKE_DESC(st + 16384u);
                uint64_t dbh = MAKE_DESC(st + 32768u);
                uint64_t dbl = MAKE_DESC(st + 49152u);
                bool en = (i > 0);
#pragma unroll
                for (int k = 0; k < 4; k++) {
                    mma_f16_ss(tmem, dah + k * 2, dbh + k * 2, GEMM_IDESC, en); en = true;
                    mma_f16_ss(tmem, dah + k * 2, dbl + k * 2, GEMM_IDESC, true);
                    mma_f16_ss(tmem, dal + k * 2, dbh + k * 2, GEMM_IDESC, true);
                }
                TCGEN05_COMMIT(mb[s]);
            }
        }
        if (i >= 1) {
            MBARRIER_WAIT_PARITY(mb[sp], ph[sp]);
            ph[sp] ^= 1;
            if (i + 2 < nblk) {
                uint32_t st = sbase + (uint32_t)sp * 65536u;
                int j = i + 2;
                load_tile16(st,          Ah + j * 64, K, tid);
                load_tile16(st + 16384u, Al + j * 64, K, tid);
                load_tile16(st + 32768u, Bh + j * 64, K, tid);
                load_tile16(st + 49152u, Bl + j * 64, K, tid);
            }
        } else if (nblk > 2) {
            uint32_t st = sbase + 2u * 65536u;
            load_tile16(st,          Ah + 2 * 64, K, tid);
            load_tile16(st + 16384u, Al + 2 * 64, K, tid);
            load_tile16(st + 32768u, Bh + 2 * 64, K, tid);
            load_tile16(st + 49152u, Bl + 2 * 64, K, tid);
        }
        CP_COMMIT();
        sp = s;
        s = (s == 2) ? 0 : s + 1;
    }

    {
        int lastS = (nblk - 1) % 3;
        MBARRIER_WAIT_PARITY(mb[lastS], ph[lastS]);
    }
    TCGEN05_FENCE_AFTER();

    if (tid < 128) {
        int row = bm + wid * 32 + lid;
#pragma unroll
        for (int cb = 0; cb < 128; cb += 32) {
            uint32_t rr[32];
            TCGEN05_LD_X32(rr, tmem + cb);
            TCGEN05_WAIT_LD();
            if (SPLIT_OUT) {
                uint32_t* hd = (uint32_t*)(Chi + (size_t)row * N + bn + cb);
                uint32_t* ld = (uint32_t*)(Clo + (size_t)row * N + bn + cb);
#pragma unroll
                for (int c = 0; c < 32; c += 2) {
                    float v0 = fmaxf(__uint_as_float(rr[c])     + bias[bn + cb + c],     0.0f);
                    float v1 = fmaxf(__uint_as_float(rr[c + 1]) + bias[bn + cb + c + 1], 0.0f);
                    uint32_t hh, ll;
                    pack_hi_lo(v0, v1, hh, ll);
                    hd[c >> 1] = hh; ld[c >> 1] = ll;
                }
            } else {
                float* cd = Cf + (size_t)row * N + bn + cb;
#pragma unroll
                for (int c = 0; c < 32; c++)
                    cd[c] = fmaxf(__uint_as_float(rr[c]) + bias[bn + cb + c], 0.0f);
            }
        }
        TCGEN05_FENCE_BEFORE();
    }
    __syncthreads();
    if (wid == 0) TCGEN05_DEALLOC(tmem, 128);

#else  // ---------------- SIMT fallback (baseline compute_103 pass) ---------
    float* As = (float*)dsm;
    float* Bs = As + 16 * 132;

    int tr = (tid >> 4) * 8;
    int tc = (tid & 15) * 8;

    float acc[8][8] = {};

    for (int k0 = 0; k0 < K; k0 += 16) {
#pragma unroll
        for (int e = 0; e < 8; e++) {
            int idx = tid * 8 + e;
            int kk = idx >> 7, rr = idx & 127;
            As[kk * 132 + rr] = __bfloat162float(Ahi[(size_t)(bm + rr) * K + k0 + kk]) +
                                __bfloat162float(Alo[(size_t)(bm + rr) * K + k0 + kk]);
            Bs[kk * 132 + rr] = __bfloat162float(Bhi[(size_t)(bn + rr) * K + k0 + kk]) +
                                __bfloat162float(Blo[(size_t)(bn + rr) * K + k0 + kk]);
        }
        __syncthreads();
#pragma unroll
        for (int k = 0; k < 16; k++) {
            float ra[8], rb[8];
#pragma unroll
            for (int i = 0; i < 8; i++) ra[i] = As[k * 132 + tr + i];
#pragma unroll
            for (int j = 0; j < 8; j++) rb[j] = Bs[k * 132 + tc + j];
#pragma unroll
            for (int i = 0; i < 8; i++)
#pragma unroll
                for (int j = 0; j < 8; j++) acc[i][j] += ra[i] * rb[j];
        }
        __syncthreads();
    }

#pragma unroll
    for (int i = 0; i < 8; i++) {
#pragma unroll
        for (int j = 0; j < 8; j += 2) {
            float v0 = fmaxf(acc[i][j]     + bias[bn + tc + j],     0.0f);
            float v1 = fmaxf(acc[i][j + 1] + bias[bn + tc + j + 1], 0.0f);
            size_t o = (size_t)(bm + tr + i) * N + bn + tc + j;
            if (SPLIT_OUT) {
                uint32_t hh, ll;
                pack_hi_lo(v0, v1, hh, ll);
                *(uint32_t*)(Chi + o) = hh;
                *(uint32_t*)(Clo + o) = ll;
            } else {
                Cf[o] = v0; Cf[o + 1] = v1;
            }
        }
    }
#endif
}

// ---------------------------------------------------------------------------
// Final projection: out[n, j] = dot(fc2[n,:], p_w[j,:]) + p_b[j], j < 20
// ---------------------------------------------------------------------------
__global__ void proj_kernel(const float* __restrict__ fc2,
                            const float* __restrict__ p_w,
                            const float* __restrict__ p_b,
                            float* __restrict__ out, int NJ) {
    __shared__ float sh[1024];
    int n = blockIdx.x;
    for (int i = threadIdx.x; i < 1024; i += blockDim.x)
        sh[i] = fc2[(size_t)n * 1024 + i];
    __syncthreads();
    int j = threadIdx.x;
    if (j < NJ) {
        const float* wrow = p_w + (size_t)j * 1024;
        float s = p_b[j];
#pragma unroll 8
        for (int k = 0; k < 1024; k++) s += sh[k] * wrow[k];
        out[(size_t)n * NJ + j] = s;
    }
}

// ---------------------------------------------------------------------------
extern "C" void kernel_launch(void* const* d_in, const int* in_sizes, int n_in,
                              void* d_out, int out_size) {
    const float* fm0   = (const float*)d_in[0];
    const float* fm1   = (const float*)d_in[1];
    const float* fm2   = (const float*)d_in[2];
    const float* fm3   = (const float*)d_in[3];
    const float* rois  = (const float*)d_in[4];
    const float* fc1_w = (const float*)d_in[5];
    const float* fc1_b = (const float*)d_in[6];
    const float* fc2_w = (const float*)d_in[7];
    const float* fc2_b = (const float*)d_in[8];
    const float* p_w   = (const float*)d_in[9];
    const float* p_b   = (const float*)d_in[10];
    float* out = (float*)d_out;

    int nrois = in_sizes[4] / 5;   // 1024
    int nj = out_size / nrois;     // 20

    static cudaStream_t s2 = nullptr;
    static cudaEvent_t evF = nullptr, evJ = nullptr;
    if (!s2) {
        cudaStreamCreateWithFlags(&s2, cudaStreamNonBlocking);
        cudaEventCreateWithFlags(&evF, cudaEventDisableTiming);
        cudaEventCreateWithFlags(&evJ, cudaEventDisableTiming);
    }

    __nv_bfloat16 *w1h, *w1l, *w2h, *w2l, *p5h, *p5l, *f1h, *f1l;
    float* fc2p;
    cudaGetSymbolAddress((void**)&w1h, g_w1_hi);
    cudaGetSymbolAddress((void**)&w1l, g_w1_lo);
    cudaGetSymbolAddress((void**)&w2h, g_w2_hi);
    cudaGetSymbolAddress((void**)&w2l, g_w2_lo);
    cudaGetSymbolAddress((void**)&p5h, g_p5_hi);
    cudaGetSymbolAddress((void**)&p5l, g_p5_lo);
    cudaGetSymbolAddress((void**)&f1h, g_fc1_hi);
    cudaGetSymbolAddress((void**)&f1l, g_fc1_lo);
    cudaGetSymbolAddress((void**)&fc2p, g_fc2);

    // Fork: weight splits run concurrent with transposes + ROI.
    cudaEventRecord(evF, 0);
    cudaStreamWaitEvent(s2, evF, 0);
    split_kernel<<<(12544 * 1024 / 4 + 255) / 256, 256, 0, s2>>>(fc1_w, w1h, w1l, 12544 * 1024 / 4);
    split_kernel<<<(1024 * 1024 / 4 + 255) / 256, 256, 0, s2>>>(fc2_w, w2h, w2l, 1024 * 1024 / 4);
    cudaEventRecord(evJ, s2);

    // Main: NCHW -> NHWC (float4 transpose, <=4 tiles/block, ceil grid).
    nchw2nhwc_kernel<<<dim3((61440 / 32 + 3) / 4, 8, 2), 256>>>(fm0, 61440, (size_t)0);
    nchw2nhwc_kernel<<<dim3((15360 / 32 + 3) / 4, 8, 2), 256>>>(fm1, 15360, (size_t)31457280);
    nchw2nhwc_kernel<<<dim3((3840 / 32 + 3) / 4, 8, 2), 256>>>(fm2, 3840, (size_t)39321600);
    nchw2nhwc_kernel<<<dim3((960 / 32 + 3) / 4, 8, 2), 256>>>(fm3, 960, (size_t)41287680);

    cudaFuncSetAttribute(roi_align_kernel,
                         cudaFuncAttributeMaxDynamicSharedMemorySize, 50176);
    roi_align_kernel<<<nrois, 256, 50176>>>(rois);

    cudaStreamWaitEvent(0, evJ, 0);

    const int GEMM_SMEM = 1024 + 3 * 65536;  // 197632 (3-stage)
    cudaFuncSetAttribute(gemm_tc<true>,
                         cudaFuncAttributeMaxDynamicSharedMemorySize, GEMM_SMEM);
    cudaFuncSetAttribute(gemm_tc<false>,
                         cudaFuncAttributeMaxDynamicSharedMemorySize, GEMM_SMEM);

    // FC1: [1024, 12544] x [1024, 12544]^T -> fc1 hi/lo
    gemm_tc<true><<<dim3(8, nrois / 128), 256, GEMM_SMEM>>>(
        p5h, p5l, w1h, w1l, fc1_b, nullptr, f1h, f1l, 1024, 12544);
    // FC2: [1024, 1024] x [1024, 1024]^T -> fc2 fp32
    gemm_tc<false><<<dim3(8, nrois / 128), 256, GEMM_SMEM>>>(
        f1h, f1l, w2h, w2l, fc2_b, fc2p, nullptr, nullptr, 1024, 1024);

    // Projection
    proj_kernel<<<nrois, 256>>>(fc2p, p_w, p_b, out, nj);
}

// round 7
// speedup vs baseline: 1.1782x; 1.1782x over previous
#include <cuda_runtime.h>
#include <cuda_bf16.h>
#include <cstdint>

// ---------------------------------------------------------------------------
// Shapes: B=2, C=256, Im 768x1280, strides {4,8,16,32}, N=1024 rois
// pool5 D = 256*49 = 12544; fc1: 12544->1024 relu; fc2: 1024->1024 relu; proj->20
// ---------------------------------------------------------------------------

#define NCH 256

#if defined(__CUDA_ARCH__) && defined(__CUDA_ARCH_FEAT_SM103_ALL)
#define HAS_TCGEN05 1
#else
#define HAS_TCGEN05 0
#endif

__device__ float g_nhwc[41779200];
__device__ __nv_bfloat16 g_p5_hi[1024 * 12544];
__device__ __nv_bfloat16 g_p5_lo[1024 * 12544];
__device__ __nv_bfloat16 g_w1_hi[1024 * 12544];
__device__ __nv_bfloat16 g_w1_lo[1024 * 12544];
__device__ __nv_bfloat16 g_fc1_hi[1024 * 1024];
__device__ __nv_bfloat16 g_fc1_lo[1024 * 1024];
__device__ __nv_bfloat16 g_w2_hi[1024 * 1024];
__device__ __nv_bfloat16 g_w2_lo[1024 * 1024];
__device__ float g_fc2[1024 * 1024];

__constant__ size_t c_lvl_off[4] = {0, 31457280, 39321600, 41287680};

// ============================ PTX helpers ==================================
__device__ __forceinline__ uint32_t smem_u32(const void* p) {
    uint32_t a;
    asm("{ .reg .u64 t; cvta.to.shared.u64 t, %1; cvt.u32.u64 %0, t; }" : "=r"(a) : "l"(p));
    return a;
}
__device__ __forceinline__ uint32_t elect_one() {
    uint32_t p;
    asm volatile("{\n\t.reg .pred p;\n\telect.sync _|p, 0xFFFFFFFF;\n\tselp.b32 %0, 1, 0, p;\n\t}" : "=r"(p));
    return p;
}
#define MBARRIER_INIT(addr, cnt) \
    asm volatile("mbarrier.init.shared.b64 [%0], %1;" :: "r"(addr), "r"(cnt) : "memory")
#define MBARRIER_WAIT_PARITY(addr, par) do {                                          \
    uint32_t _m = (addr); uint32_t _p = (par); uint32_t _d;                           \
    asm volatile("{\n\t.reg .pred p;\n\t"                                             \
        "mbarrier.try_wait.parity.acquire.cta.shared::cta.b64 p, [%1], %2;\n\t"       \
        "selp.b32 %0, 1, 0, p;\n\t}" : "=r"(_d) : "r"(_m), "r"(_p) : "memory");       \
    if (!_d) {                                                                        \
        asm volatile("{\n\t.reg .pred P1;\n\t"                                        \
            "WL_%=:\n\t"                                                              \
            "mbarrier.try_wait.parity.acquire.cta.shared::cta.b64 P1, [%0], %1, 0x989680;\n\t" \
            "@P1 bra.uni WD_%=;\n\tbra.uni WL_%=;\n\tWD_%=:\n\t}"                     \
            :: "r"(_m), "r"(_p) : "memory");                                          \
    } } while (0)
#define FENCE_PROXY_ASYNC() asm volatile("fence.proxy.async.shared::cta;" ::: "memory")
#define CP_COMMIT() asm volatile("cp.async.commit_group;" ::: "memory")
#define CP_WAIT_1() asm volatile("cp.async.wait_group 1;" ::: "memory")

#if HAS_TCGEN05
#define TCGEN05_ALLOC(sa, n) \
    asm volatile("tcgen05.alloc.cta_group::1.sync.aligned.shared::cta.b32 [%0], %1;" :: "r"(sa), "r"(n) : "memory")
#define TCGEN05_DEALLOC(t, n) \
    asm volatile("tcgen05.dealloc.cta_group::1.sync.aligned.b32 %0, %1;" :: "r"(t), "r"(n))
#define TCGEN05_RELINQ() \
    asm volatile("tcgen05.relinquish_alloc_permit.cta_group::1.sync.aligned;")
#define TCGEN05_COMMIT(mb) \
    asm volatile("tcgen05.commit.cta_group::1.mbarrier::arrive::one.shared::cluster.b64 [%0];" :: "r"(mb) : "memory")
#define TCGEN05_FENCE_AFTER()  asm volatile("tcgen05.fence::after_thread_sync;" ::: "memory")
#define TCGEN05_FENCE_BEFORE() asm volatile("tcgen05.fence::before_thread_sync;" ::: "memory")
#define TCGEN05_WAIT_LD() asm volatile("tcgen05.wait::ld.sync.aligned;" ::: "memory")

#define TCGEN05_LD_X32(r, ta)                                                          \
    asm volatile("tcgen05.ld.sync.aligned.32x32b.x32.b32 "                             \
        "{%0, %1, %2, %3, %4, %5, %6, %7, %8, %9, %10, %11, %12, %13, %14, %15, "      \
        " %16, %17, %18, %19, %20, %21, %22, %23, %24, %25, %26, %27, %28, %29, %30, %31}, [%32];" \
        : "=r"((r)[0]), "=r"((r)[1]), "=r"((r)[2]), "=r"((r)[3]),                      \
          "=r"((r)[4]), "=r"((r)[5]), "=r"((r)[6]), "=r"((r)[7]),                      \
          "=r"((r)[8]), "=r"((r)[9]), "=r"((r)[10]), "=r"((r)[11]),                    \
          "=r"((r)[12]), "=r"((r)[13]), "=r"((r)[14]), "=r"((r)[15]),                  \
          "=r"((r)[16]), "=r"((r)[17]), "=r"((r)[18]), "=r"((r)[19]),                  \
          "=r"((r)[20]), "=r"((r)[21]), "=r"((r)[22]), "=r"((r)[23]),                  \
          "=r"((r)[24]), "=r"((r)[25]), "=r"((r)[26]), "=r"((r)[27]),                  \
          "=r"((r)[28]), "=r"((r)[29]), "=r"((r)[30]), "=r"((r)[31])                   \
        : "r"(ta))

__device__ __forceinline__ void mma_f16_ss(uint32_t d, uint64_t a, uint64_t b,
                                           uint32_t idesc, bool en) {
    uint32_t e = en ? 1u : 0u;
    asm volatile(
        "{\n\t.reg .pred p;\n\tsetp.ne.u32 p, %4, 0;\n\t"
        "tcgen05.mma.cta_group::1.kind::f16 [%0], %1, %2, %3, {%5, %5, %5, %5}, p;\n\t}"
        :: "r"(d), "l"(a), "l"(b), "r"(idesc), "r"(e), "r"(0u) : "memory");
}
#endif  // HAS_TCGEN05

// SW128 K-major descriptor: layout=2, version=1, SBO=64, LBO=1
static constexpr uint64_t DESC_BASE_SW128 =
    (uint64_t(2) << 61) | (uint64_t(1) << 46) | (uint64_t(64) << 32) | (uint64_t(1) << 16);
#define MAKE_DESC(a) (DESC_BASE_SW128 | ((uint64_t)((a) >> 4) & 0x3FFF))

// idesc kind::f16: F32 accum, BF16 a/b, M=128, N=128
static constexpr uint32_t GEMM_IDESC =
    (1u << 4) | (1u << 7) | (1u << 10) | ((128u / 8u) << 17) | ((128u / 16u) << 24);

__device__ __forceinline__ void pack_hi_lo(float v0, float v1, uint32_t& h, uint32_t& l) {
    asm("cvt.rn.bf16x2.f32 %0, %1, %2;" : "=r"(h) : "f"(v1), "f"(v0));
    float l0 = v0 - __uint_as_float(h << 16);
    float l1 = v1 - __uint_as_float(h & 0xffff0000u);
    asm("cvt.rn.bf16x2.f32 %0, %1, %2;" : "=r"(l) : "f"(l1), "f"(l0));
}

// ---------------------------------------------------------------------------
// NCHW -> NHWC transpose: 4 tiles/block, ALL 4 LDG.128 issued before the
// single sync (MLP=4/thread), then 4 STG.128. Uniform tail guard.
// ---------------------------------------------------------------------------
__global__ void nchw2nhwc_kernel(const float* __restrict__ in, int HW, size_t off) {
    __shared__ float tile[4][32][33];
    int b = blockIdx.z;
    int c0 = blockIdx.y * 32;
    int t = threadIdx.x;            // 256
    int cr  = t >> 3;               // 0..31
    int f4  = t & 7;                // 0..7

    int hwbase = blockIdx.x * 128;
    int nrep = (HW - hwbase + 31) >> 5;      // uniform; 1..4
    if (nrep > 4) nrep = 4;

    float4 v[4];
#pragma unroll
    for (int rep = 0; rep < 4; rep++)
        if (rep < nrep)
            v[rep] = *((const float4*)(in + ((size_t)b * NCH + c0 + cr) * HW + hwbase + rep * 32) + f4);

#pragma unroll
    for (int rep = 0; rep < 4; rep++)
        if (rep < nrep) {
            tile[rep][f4 * 4 + 0][cr] = v[rep].x;
            tile[rep][f4 * 4 + 1][cr] = v[rep].y;
            tile[rep][f4 * 4 + 2][cr] = v[rep].z;
            tile[rep][f4 * 4 + 3][cr] = v[rep].w;
        }
    __syncthreads();

#pragma unroll
    for (int rep = 0; rep < 4; rep++)
        if (rep < nrep) {
            float4 o;
            o.x = tile[rep][cr][f4 * 4 + 0];
            o.y = tile[rep][cr][f4 * 4 + 1];
            o.z = tile[rep][cr][f4 * 4 + 2];
            o.w = tile[rep][cr][f4 * 4 + 3];
            *((float4*)(g_nhwc + off + ((size_t)b * HW + hwbase + rep * 32 + cr) * NCH + c0) + f4) = o;
        }
}

// ---------------------------------------------------------------------------
// ROIAlign: one block per roi. 64 channel-quads (float4) x 4 bin-groups.
// tid = grp*64 + c4: thread handles channels [4*c4, 4*c4+4) for bins
// {grp, grp+4, ...}. 4x fewer LDG, 4x MLP vs scalar-channel version.
// ---------------------------------------------------------------------------
__global__ void roi_align_kernel(const float* __restrict__ rois) {
    extern __shared__ float shbuf[];  // 12544 floats, [channel*49 + bin]
    __shared__ int   s_ix0[14], s_ix1[14], s_iy0[14], s_iy1[14];
    __shared__ float s_wx0[14], s_wx1[14], s_wy0[14], s_wy1[14];

    int n = blockIdx.x;
    int tid = threadIdx.x;
    int c4  = tid & 63;   // channel quad 0..63
    int grp = tid >> 6;   // 0..3

    const float* r = rois + (size_t)n * 5;
    int   b  = (int)r[0];
    float x1 = r[1], y1 = r[2], x2 = r[3], y2 = r[4];

    float w = x2 - x1, h = y2 - y1;
    float kf = floorf(4.0f + log2f(sqrtf(fmaxf(w * h, 1e-6f)) / 224.0f));
    kf = fminf(fmaxf(kf, 2.0f), 5.0f);
    int lvl = (int)kf - 2;

    float stride = (float)(4 << lvl);
    int H = 768 >> (lvl + 2);
    int W = 1280 >> (lvl + 2);
    const float4* base4 = (const float4*)(g_nhwc + c_lvl_off[lvl] + ((size_t)b * H * W) * NCH);

    if (tid < 28) {
        bool isx = tid < 14;
        int  s   = isx ? tid : tid - 14;
        float lo = isx ? x1 : y1;
        float hi = isx ? x2 : y2;
        int size = isx ? W : H;
        float a = lo / stride - 0.5f;
        float bb = hi / stride - 0.5f;
        float coord = a + (bb - a) * (((float)s + 0.5f) / 14.0f);
        float valid = (coord > -1.0f && coord < (float)size) ? 1.0f : 0.0f;
        float cc = fminf(fmaxf(coord, 0.0f), (float)(size - 1));
        int i0 = (int)floorf(cc);
        int i1 = min(i0 + 1, size - 1);
        float frac = cc - (float)i0;
        if (isx) { s_ix0[s] = i0; s_ix1[s] = i1; s_wx0[s] = (1.0f - frac) * valid; s_wx1[s] = frac * valid; }
        else     { s_iy0[s] = i0; s_iy1[s] = i1; s_wy0[s] = (1.0f - frac) * valid; s_wy1[s] = frac * valid; }
    }
    __syncthreads();

    for (int bin = grp; bin < 49; bin += 4) {
        int by = bin / 7, bx = bin - by * 7;
        float ax = 0.0f, ay = 0.0f, az = 0.0f, aw = 0.0f;
#pragma unroll
        for (int i = 0; i < 2; i++) {
            int sy = by * 2 + i;
            float wy0 = s_wy0[sy], wy1 = s_wy1[sy];
            int row0 = s_iy0[sy] * W;
            int row1 = s_iy1[sy] * W;
#pragma unroll
            for (int j = 0; j < 2; j++) {
                int sx = bx * 2 + j;
                float wx0 = s_wx0[sx], wx1 = s_wx1[sx];
                int xa = s_ix0[sx], xb = s_ix1[sx];
                float4 v00 = __ldg(base4 + (size_t)(row0 + xa) * 64 + c4);
                float4 v01 = __ldg(base4 + (size_t)(row0 + xb) * 64 + c4);
                float4 v10 = __ldg(base4 + (size_t)(row1 + xa) * 64 + c4);
                float4 v11 = __ldg(base4 + (size_t)(row1 + xb) * 64 + c4);
                float w00 = wy0 * wx0, w01 = wy0 * wx1, w10 = wy1 * wx0, w11 = wy1 * wx1;
                ax += w00 * v00.x + w01 * v01.x + w10 * v10.x + w11 * v11.x;
                ay += w00 * v00.y + w01 * v01.y + w10 * v10.y + w11 * v11.y;
                az += w00 * v00.z + w01 * v01.z + w10 * v10.z + w11 * v11.z;
                aw += w00 * v00.w + w01 * v01.w + w10 * v10.w + w11 * v11.w;
            }
        }
        int ch = c4 * 4;
        shbuf[(ch + 0) * 49 + bin] = ax * 0.25f;
        shbuf[(ch + 1) * 49 + bin] = ay * 0.25f;
        shbuf[(ch + 2) * 49 + bin] = az * 0.25f;
        shbuf[(ch + 3) * 49 + bin] = aw * 0.25f;
    }
    __syncthreads();

    uint32_t* hd = (uint32_t*)(g_p5_hi + (size_t)n * 12544);
    uint32_t* ld = (uint32_t*)(g_p5_lo + (size_t)n * 12544);
    for (int i = tid; i < 6272; i += 256) {
        float v0 = shbuf[2 * i], v1 = shbuf[2 * i + 1];
        uint32_t hh, ll;
        pack_hi_lo(v0, v1, hh, ll);
        hd[i] = hh; ld[i] = ll;
    }
}

// ---------------------------------------------------------------------------
// fp32 -> bf16 hi/lo split (for weights)
// ---------------------------------------------------------------------------
__global__ void split_kernel(const float* __restrict__ in,
                             __nv_bfloat16* __restrict__ hi,
                             __nv_bfloat16* __restrict__ lo, int n4) {
    int i = blockIdx.x * blockDim.x + threadIdx.x;
    if (i >= n4) return;
    float4 v = ((const float4*)in)[i];
    uint32_t h0, h1, l0, l1;
    pack_hi_lo(v.x, v.y, h0, l0);
    pack_hi_lo(v.z, v.w, h1, l1);
    ((uint2*)hi)[i] = make_uint2(h0, h1);
    ((uint2*)lo)[i] = make_uint2(l0, l1);
}

// ---------------------------------------------------------------------------
// GEMM: C[M,N] = A[M,K] @ B[N,K]^T + bias, ReLU.
// sm_103a: tcgen05, D = Ah*Bh + Ah*Bl + Al*Bh, fp32 TMEM accumulation.
// 128x128 tile, BK=64, 256 threads, cp.async 3-stage pipeline with lagged
// MMA-completion wait.
// ---------------------------------------------------------------------------
__device__ __forceinline__ void load_tile16(uint32_t s_tile, const __nv_bfloat16* g,
                                            int ldK, int tid) {
#pragma unroll
    for (int q = 0; q < 4; q++) {
        int gid = tid + q * 256;
        int row = gid >> 3, c16 = gid & 7;
        uint32_t dst = s_tile + row * 128 + ((c16 ^ (row & 7)) << 4);
        const char* src = (const char*)(g + (size_t)row * ldK) + (c16 << 4);
        asm volatile("cp.async.cg.shared.global [%0], [%1], 16;" :: "r"(dst), "l"(src) : "memory");
    }
}

template <bool SPLIT_OUT>
__global__ __launch_bounds__(256, 1) void gemm_tc(
    const __nv_bfloat16* __restrict__ Ahi, const __nv_bfloat16* __restrict__ Alo,
    const __nv_bfloat16* __restrict__ Bhi, const __nv_bfloat16* __restrict__ Blo,
    const float* __restrict__ bias,
    float* __restrict__ Cf, __nv_bfloat16* __restrict__ Chi, __nv_bfloat16* __restrict__ Clo,
    int N, int K) {
    extern __shared__ char dsm[];
    int tid = threadIdx.x;
    int bm = blockIdx.y * 128, bn = blockIdx.x * 128;

#if HAS_TCGEN05
    __shared__ uint32_t s_tmem;
    __shared__ uint64_t s_mbar[3];

    uint32_t sbase = (smem_u32(dsm) + 1023u) & ~1023u;
    int wid = tid >> 5, lid = tid & 31;

    uint32_t mb[3] = { smem_u32(&s_mbar[0]), smem_u32(&s_mbar[1]), smem_u32(&s_mbar[2]) };

    if (wid == 0) TCGEN05_ALLOC(smem_u32(&s_tmem), 128);
    if (tid == 0) { MBARRIER_INIT(mb[0], 1); MBARRIER_INIT(mb[1], 1); MBARRIER_INIT(mb[2], 1); }
    __syncthreads();
    uint32_t tmem = s_tmem;
    if (wid == 0) TCGEN05_RELINQ();

    const int nblk = K >> 6;

    const __nv_bfloat16* Ah = Ahi + (size_t)bm * K;
    const __nv_bfloat16* Al = Alo + (size_t)bm * K;
    const __nv_bfloat16* Bh = Bhi + (size_t)bn * K;
    const __nv_bfloat16* Bl = Blo + (size_t)bn * K;

#pragma unroll
    for (int p = 0; p < 2; p++) {
        uint32_t st = sbase + (uint32_t)p * 65536u;
        load_tile16(st,          Ah + p * 64, K, tid);
        load_tile16(st + 16384u, Al + p * 64, K, tid);
        load_tile16(st + 32768u, Bh + p * 64, K, tid);
        load_tile16(st + 49152u, Bl + p * 64, K, tid);
        CP_COMMIT();
    }

    int ph[3] = {0, 0, 0};
    int s = 0, sp = 2;
    for (int i = 0; i < nblk; i++) {
        CP_WAIT_1();
        __syncthreads();
        if (tid < 32) {
            if (elect_one()) {
                FENCE_PROXY_ASYNC();
                uint32_t st = sbase + (uint32_t)s * 65536u;
                uint64_t dah = MAKE_DESC(st);
                uint64_t dal = MAKE_DESC(st + 16384u);
                uint64_t dbh = MAKE_DESC(st + 32768u);
                uint64_t dbl = MAKE_DESC(st + 49152u);
                bool en = (i > 0);
#pragma unroll
                for (int k = 0; k < 4; k++) {
                    mma_f16_ss(tmem, dah + k * 2, dbh + k * 2, GEMM_IDESC, en); en = true;
                    mma_f16_ss(tmem, dah + k * 2, dbl + k * 2, GEMM_IDESC, true);
                    mma_f16_ss(tmem, dal + k * 2, dbh + k * 2, GEMM_IDESC, true);
                }
                TCGEN05_COMMIT(mb[s]);
            }
        }
        if (i >= 1) {
            MBARRIER_WAIT_PARITY(mb[sp], ph[sp]);
            ph[sp] ^= 1;
            if (i + 2 < nblk) {
                uint32_t st = sbase + (uint32_t)sp * 65536u;
                int j = i + 2;
                load_tile16(st,          Ah + j * 64, K, tid);
                load_tile16(st + 16384u, Al + j * 64, K, tid);
                load_tile16(st + 32768u, Bh + j * 64, K, tid);
                load_tile16(st + 49152u, Bl + j * 64, K, tid);
            }
        } else if (nblk > 2) {
            uint32_t st = sbase + 2u * 65536u;
            load_tile16(st,          Ah + 2 * 64, K, tid);
            load_tile16(st + 16384u, Al + 2 * 64, K, tid);
            load_tile16(st + 32768u, Bh + 2 * 64, K, tid);
            load_tile16(st + 49152u, Bl + 2 * 64, K, tid);
        }
        CP_COMMIT();
        sp = s;
        s = (s == 2) ? 0 : s + 1;
    }

    {
        int lastS = (nblk - 1) % 3;
        MBARRIER_WAIT_PARITY(mb[lastS], ph[lastS]);
    }
    TCGEN05_FENCE_AFTER();

    if (tid < 128) {
        int row = bm + wid * 32 + lid;
#pragma unroll
        for (int cb = 0; cb < 128; cb += 32) {
            uint32_t rr[32];
            TCGEN05_LD_X32(rr, tmem + cb);
            TCGEN05_WAIT_LD();
            if (SPLIT_OUT) {
                uint32_t* hd = (uint32_t*)(Chi + (size_t)row * N + bn + cb);
                uint32_t* ld = (uint32_t*)(Clo + (size_t)row * N + bn + cb);
#pragma unroll
                for (int c = 0; c < 32; c += 2) {
                    float v0 = fmaxf(__uint_as_float(rr[c])     + bias[bn + cb + c],     0.0f);
                    float v1 = fmaxf(__uint_as_float(rr[c + 1]) + bias[bn + cb + c + 1], 0.0f);
                    uint32_t hh, ll;
                    pack_hi_lo(v0, v1, hh, ll);
                    hd[c >> 1] = hh; ld[c >> 1] = ll;
                }
            } else {
                float* cd = Cf + (size_t)row * N + bn + cb;
#pragma unroll
                for (int c = 0; c < 32; c++)
                    cd[c] = fmaxf(__uint_as_float(rr[c]) + bias[bn + cb + c], 0.0f);
            }
        }
        TCGEN05_FENCE_BEFORE();
    }
    __syncthreads();
    if (wid == 0) TCGEN05_DEALLOC(tmem, 128);

#else  // ---------------- SIMT fallback (baseline compute_103 pass) ---------
    float* As = (float*)dsm;
    float* Bs = As + 16 * 132;

    int tr = (tid >> 4) * 8;
    int tc = (tid & 15) * 8;

    float acc[8][8] = {};

    for (int k0 = 0; k0 < K; k0 += 16) {
#pragma unroll
        for (int e = 0; e < 8; e++) {
            int idx = tid * 8 + e;
            int kk = idx >> 7, rr = idx & 127;
            As[kk * 132 + rr] = __bfloat162float(Ahi[(size_t)(bm + rr) * K + k0 + kk]) +
                                __bfloat162float(Alo[(size_t)(bm + rr) * K + k0 + kk]);
            Bs[kk * 132 + rr] = __bfloat162float(Bhi[(size_t)(bn + rr) * K + k0 + kk]) +
                                __bfloat162float(Blo[(size_t)(bn + rr) * K + k0 + kk]);
        }
        __syncthreads();
#pragma unroll
        for (int k = 0; k < 16; k++) {
            float ra[8], rb[8];
#pragma unroll
            for (int i = 0; i < 8; i++) ra[i] = As[k * 132 + tr + i];
#pragma unroll
            for (int j = 0; j < 8; j++) rb[j] = Bs[k * 132 + tc + j];
#pragma unroll
            for (int i = 0; i < 8; i++)
#pragma unroll
                for (int j = 0; j < 8; j++) acc[i][j] += ra[i] * rb[j];
        }
        __syncthreads();
    }

#pragma unroll
    for (int i = 0; i < 8; i++) {
#pragma unroll
        for (int j = 0; j < 8; j += 2) {
            float v0 = fmaxf(acc[i][j]     + bias[bn + tc + j],     0.0f);
            float v1 = fmaxf(acc[i][j + 1] + bias[bn + tc + j + 1], 0.0f);
            size_t o = (size_t)(bm + tr + i) * N + bn + tc + j;
            if (SPLIT_OUT) {
                uint32_t hh, ll;
                pack_hi_lo(v0, v1, hh, ll);
                *(uint32_t*)(Chi + o) = hh;
                *(uint32_t*)(Clo + o) = ll;
            } else {
                Cf[o] = v0; Cf[o + 1] = v1;
            }
        }
    }
#endif
}

// ---------------------------------------------------------------------------
// Final projection: out[n, j] = dot(fc2[n,:], p_w[j,:]) + p_b[j], j < 20
// ---------------------------------------------------------------------------
__global__ void proj_kernel(const float* __restrict__ fc2,
                            const float* __restrict__ p_w,
                            const float* __restrict__ p_b,
                            float* __restrict__ out, int NJ) {
    __shared__ float sh[1024];
    int n = blockIdx.x;
    for (int i = threadIdx.x; i < 1024; i += blockDim.x)
        sh[i] = fc2[(size_t)n * 1024 + i];
    __syncthreads();
    int j = threadIdx.x;
    if (j < NJ) {
        const float* wrow = p_w + (size_t)j * 1024;
        float s = p_b[j];
#pragma unroll 8
        for (int k = 0; k < 1024; k++) s += sh[k] * wrow[k];
        out[(size_t)n * NJ + j] = s;
    }
}

// ---------------------------------------------------------------------------
extern "C" void kernel_launch(void* const* d_in, const int* in_sizes, int n_in,
                              void* d_out, int out_size) {
    const float* fm0   = (const float*)d_in[0];
    const float* fm1   = (const float*)d_in[1];
    const float* fm2   = (const float*)d_in[2];
    const float* fm3   = (const float*)d_in[3];
    const float* rois  = (const float*)d_in[4];
    const float* fc1_w = (const float*)d_in[5];
    const float* fc1_b = (const float*)d_in[6];
    const float* fc2_w = (const float*)d_in[7];
    const float* fc2_b = (const float*)d_in[8];
    const float* p_w   = (const float*)d_in[9];
    const float* p_b   = (const float*)d_in[10];
    float* out = (float*)d_out;

    int nrois = in_sizes[4] / 5;   // 1024
    int nj = out_size / nrois;     // 20

    static cudaStream_t s2 = nullptr;
    static cudaEvent_t evF = nullptr, evJ = nullptr;
    if (!s2) {
        cudaStreamCreateWithFlags(&s2, cudaStreamNonBlocking);
        cudaEventCreateWithFlags(&evF, cudaEventDisableTiming);
        cudaEventCreateWithFlags(&evJ, cudaEventDisableTiming);
    }

    __nv_bfloat16 *w1h, *w1l, *w2h, *w2l, *p5h, *p5l, *f1h, *f1l;
    float* fc2p;
    cudaGetSymbolAddress((void**)&w1h, g_w1_hi);
    cudaGetSymbolAddress((void**)&w1l, g_w1_lo);
    cudaGetSymbolAddress((void**)&w2h, g_w2_hi);
    cudaGetSymbolAddress((void**)&w2l, g_w2_lo);
    cudaGetSymbolAddress((void**)&p5h, g_p5_hi);
    cudaGetSymbolAddress((void**)&p5l, g_p5_lo);
    cudaGetSymbolAddress((void**)&f1h, g_fc1_hi);
    cudaGetSymbolAddress((void**)&f1l, g_fc1_lo);
    cudaGetSymbolAddress((void**)&fc2p, g_fc2);

    // Fork: weight splits run concurrent with transposes + ROI.
    cudaEventRecord(evF, 0);
    cudaStreamWaitEvent(s2, evF, 0);
    split_kernel<<<(12544 * 1024 / 4 + 255) / 256, 256, 0, s2>>>(fc1_w, w1h, w1l, 12544 * 1024 / 4);
    split_kernel<<<(1024 * 1024 / 4 + 255) / 256, 256, 0, s2>>>(fc2_w, w2h, w2l, 1024 * 1024 / 4);
    cudaEventRecord(evJ, s2);

    // Main: NCHW -> NHWC (4 tiles/block, MLP=4), then ROIAlign.
    nchw2nhwc_kernel<<<dim3((61440 / 32 + 3) / 4, 8, 2), 256>>>(fm0, 61440, (size_t)0);
    nchw2nhwc_kernel<<<dim3((15360 / 32 + 3) / 4, 8, 2), 256>>>(fm1, 15360, (size_t)31457280);
    nchw2nhwc_kernel<<<dim3((3840 / 32 + 3) / 4, 8, 2), 256>>>(fm2, 3840, (size_t)39321600);
    nchw2nhwc_kernel<<<dim3((960 / 32 + 3) / 4, 8, 2), 256>>>(fm3, 960, (size_t)41287680);

    cudaFuncSetAttribute(roi_align_kernel,
                         cudaFuncAttributeMaxDynamicSharedMemorySize, 50176);
    roi_align_kernel<<<nrois, 256, 50176>>>(rois);

    cudaStreamWaitEvent(0, evJ, 0);

    const int GEMM_SMEM = 1024 + 3 * 65536;  // 197632 (3-stage)
    cudaFuncSetAttribute(gemm_tc<true>,
                         cudaFuncAttributeMaxDynamicSharedMemorySize, GEMM_SMEM);
    cudaFuncSetAttribute(gemm_tc<false>,
                         cudaFuncAttributeMaxDynamicSharedMemorySize, GEMM_SMEM);

    // FC1: [1024, 12544] x [1024, 12544]^T -> fc1 hi/lo
    gemm_tc<true><<<dim3(8, nrois / 128), 256, GEMM_SMEM>>>(
        p5h, p5l, w1h, w1l, fc1_b, nullptr, f1h, f1l, 1024, 12544);
    // FC2: [1024, 1024] x [1024, 1024]^T -> fc2 fp32
    gemm_tc<false><<<dim3(8, nrois / 128), 256, GEMM_SMEM>>>(
        f1h, f1l, w2h, w2l, fc2_b, fc2p, nullptr, nullptr, 1024, 1024);

    // Projection
    proj_kernel<<<nrois, 256>>>(fc2p, p_w, p_b, out, nj);
}

// round 8
// speedup vs baseline: 1.2897x; 1.0946x over previous
#include <cuda_runtime.h>
#include <cuda_bf16.h>
#include <cuda_fp16.h>
#include <cstdint>

// ---------------------------------------------------------------------------
// Shapes: B=2, C=256, Im 768x1280, strides {4,8,16,32}, N=1024 rois
// pool5 D = 256*49 = 12544; fc1: 12544->1024 relu; fc2: 1024->1024 relu; proj->20
// ---------------------------------------------------------------------------

#define NCH 256

#if defined(__CUDA_ARCH__) && defined(__CUDA_ARCH_FEAT_SM103_ALL)
#define HAS_TCGEN05 1
#else
#define HAS_TCGEN05 0
#endif

__device__ __half g_nhwc[41779200];          // fp16 NHWC staging
__device__ __nv_bfloat16 g_p5_hi[1024 * 12544];
__device__ __nv_bfloat16 g_p5_lo[1024 * 12544];
__device__ __nv_bfloat16 g_w1_hi[1024 * 12544];
__device__ __nv_bfloat16 g_w1_lo[1024 * 12544];
__device__ __nv_bfloat16 g_fc1_hi[1024 * 1024];
__device__ __nv_bfloat16 g_fc1_lo[1024 * 1024];
__device__ __nv_bfloat16 g_w2_hi[1024 * 1024];
__device__ __nv_bfloat16 g_w2_lo[1024 * 1024];
__device__ float g_fc2[1024 * 1024];

__constant__ size_t c_lvl_off[4] = {0, 31457280, 39321600, 41287680};

// ============================ PTX helpers ==================================
__device__ __forceinline__ uint32_t smem_u32(const void* p) {
    uint32_t a;
    asm("{ .reg .u64 t; cvta.to.shared.u64 t, %1; cvt.u32.u64 %0, t; }" : "=r"(a) : "l"(p));
    return a;
}
__device__ __forceinline__ uint32_t elect_one() {
    uint32_t p;
    asm volatile("{\n\t.reg .pred p;\n\telect.sync _|p, 0xFFFFFFFF;\n\tselp.b32 %0, 1, 0, p;\n\t}" : "=r"(p));
    return p;
}
#define MBARRIER_INIT(addr, cnt) \
    asm volatile("mbarrier.init.shared.b64 [%0], %1;" :: "r"(addr), "r"(cnt) : "memory")
#define MBARRIER_WAIT_PARITY(addr, par) do {                                          \
    uint32_t _m = (addr); uint32_t _p = (par); uint32_t _d;                           \
    asm volatile("{\n\t.reg .pred p;\n\t"                                             \
        "mbarrier.try_wait.parity.acquire.cta.shared::cta.b64 p, [%1], %2;\n\t"       \
        "selp.b32 %0, 1, 0, p;\n\t}" : "=r"(_d) : "r"(_m), "r"(_p) : "memory");       \
    if (!_d) {                                                                        \
        asm volatile("{\n\t.reg .pred P1;\n\t"                                        \
            "WL_%=:\n\t"                                                              \
            "mbarrier.try_wait.parity.acquire.cta.shared::cta.b64 P1, [%0], %1, 0x989680;\n\t" \
            "@P1 bra.uni WD_%=;\n\tbra.uni WL_%=;\n\tWD_%=:\n\t}"                     \
            :: "r"(_m), "r"(_p) : "memory");                                          \
    } } while (0)
#define FENCE_PROXY_ASYNC() asm volatile("fence.proxy.async.shared::cta;" ::: "memory")
#define CP_COMMIT() asm volatile("cp.async.commit_group;" ::: "memory")
#define CP_WAIT_1() asm volatile("cp.async.wait_group 1;" ::: "memory")

#if HAS_TCGEN05
#define TCGEN05_ALLOC(sa, n) \
    asm volatile("tcgen05.alloc.cta_group::1.sync.aligned.shared::cta.b32 [%0], %1;" :: "r"(sa), "r"(n) : "memory")
#define TCGEN05_DEALLOC(t, n) \
    asm volatile("tcgen05.dealloc.cta_group::1.sync.aligned.b32 %0, %1;" :: "r"(t), "r"(n))
#define TCGEN05_RELINQ() \
    asm volatile("tcgen05.relinquish_alloc_permit.cta_group::1.sync.aligned;")
#define TCGEN05_COMMIT(mb) \
    asm volatile("tcgen05.commit.cta_group::1.mbarrier::arrive::one.shared::cluster.b64 [%0];" :: "r"(mb) : "memory")
#define TCGEN05_FENCE_AFTER()  asm volatile("tcgen05.fence::after_thread_sync;" ::: "memory")
#define TCGEN05_FENCE_BEFORE() asm volatile("tcgen05.fence::before_thread_sync;" ::: "memory")
#define TCGEN05_WAIT_LD() asm volatile("tcgen05.wait::ld.sync.aligned;" ::: "memory")

#define TCGEN05_LD_X32(r, ta)                                                          \
    asm volatile("tcgen05.ld.sync.aligned.32x32b.x32.b32 "                             \
        "{%0, %1, %2, %3, %4, %5, %6, %7, %8, %9, %10, %11, %12, %13, %14, %15, "      \
        " %16, %17, %18, %19, %20, %21, %22, %23, %24, %25, %26, %27, %28, %29, %30, %31}, [%32];" \
        : "=r"((r)[0]), "=r"((r)[1]), "=r"((r)[2]), "=r"((r)[3]),                      \
          "=r"((r)[4]), "=r"((r)[5]), "=r"((r)[6]), "=r"((r)[7]),                      \
          "=r"((r)[8]), "=r"((r)[9]), "=r"((r)[10]), "=r"((r)[11]),                    \
          "=r"((r)[12]), "=r"((r)[13]), "=r"((r)[14]), "=r"((r)[15]),                  \
          "=r"((r)[16]), "=r"((r)[17]), "=r"((r)[18]), "=r"((r)[19]),                  \
          "=r"((r)[20]), "=r"((r)[21]), "=r"((r)[22]), "=r"((r)[23]),                  \
          "=r"((r)[24]), "=r"((r)[25]), "=r"((r)[26]), "=r"((r)[27]),                  \
          "=r"((r)[28]), "=r"((r)[29]), "=r"((r)[30]), "=r"((r)[31])                   \
        : "r"(ta))

__device__ __forceinline__ void mma_f16_ss(uint32_t d, uint64_t a, uint64_t b,
                                           uint32_t idesc, bool en) {
    uint32_t e = en ? 1u : 0u;
    asm volatile(
        "{\n\t.reg .pred p;\n\tsetp.ne.u32 p, %4, 0;\n\t"
        "tcgen05.mma.cta_group::1.kind::f16 [%0], %1, %2, %3, {%5, %5, %5, %5}, p;\n\t}"
        :: "r"(d), "l"(a), "l"(b), "r"(idesc), "r"(e), "r"(0u) : "memory");
}
#endif  // HAS_TCGEN05

// SW128 K-major descriptor: layout=2, version=1, SBO=64, LBO=1
static constexpr uint64_t DESC_BASE_SW128 =
    (uint64_t(2) << 61) | (uint64_t(1) << 46) | (uint64_t(64) << 32) | (uint64_t(1) << 16);
#define MAKE_DESC(a) (DESC_BASE_SW128 | ((uint64_t)((a) >> 4) & 0x3FFF))

// idesc kind::f16: F32 accum, BF16 a/b, M=128, N=128
static constexpr uint32_t GEMM_IDESC =
    (1u << 4) | (1u << 7) | (1u << 10) | ((128u / 8u) << 17) | ((128u / 16u) << 24);

__device__ __forceinline__ void pack_hi_lo(float v0, float v1, uint32_t& h, uint32_t& l) {
    asm("cvt.rn.bf16x2.f32 %0, %1, %2;" : "=r"(h) : "f"(v1), "f"(v0));
    float l0 = v0 - __uint_as_float(h << 16);
    float l1 = v1 - __uint_as_float(h & 0xffff0000u);
    asm("cvt.rn.bf16x2.f32 %0, %1, %2;" : "=r"(l) : "f"(l1), "f"(l0));
}

// ---------------------------------------------------------------------------
// NCHW fp32 -> NHWC fp16: 8 tiles (32C x 32HW)/block, all LDG.128 issued
// before one sync (MLP=8), convert to fp16 on store (STG.64).
// ---------------------------------------------------------------------------
__global__ void nchw2nhwc_kernel(const float* __restrict__ in, int HW, size_t off) {
    __shared__ float tile[8][32][33];
    int b = blockIdx.z;
    int c0 = blockIdx.y * 32;
    int t = threadIdx.x;            // 256
    int cr  = t >> 3;               // 0..31
    int f4  = t & 7;                // 0..7

    int hwbase = blockIdx.x * 256;
    int nrep = (HW - hwbase + 31) >> 5;      // uniform; 1..8
    if (nrep > 8) nrep = 8;

    float4 v[8];
#pragma unroll
    for (int rep = 0; rep < 8; rep++)
        if (rep < nrep)
            v[rep] = *((const float4*)(in + ((size_t)b * NCH + c0 + cr) * HW + hwbase + rep * 32) + f4);

#pragma unroll
    for (int rep = 0; rep < 8; rep++)
        if (rep < nrep) {
            tile[rep][f4 * 4 + 0][cr] = v[rep].x;
            tile[rep][f4 * 4 + 1][cr] = v[rep].y;
            tile[rep][f4 * 4 + 2][cr] = v[rep].z;
            tile[rep][f4 * 4 + 3][cr] = v[rep].w;
        }
    __syncthreads();

#pragma unroll
    for (int rep = 0; rep < 8; rep++)
        if (rep < nrep) {
            half2 a = __floats2half2_rn(tile[rep][cr][f4 * 4 + 0], tile[rep][cr][f4 * 4 + 1]);
            half2 c = __floats2half2_rn(tile[rep][cr][f4 * 4 + 2], tile[rep][cr][f4 * 4 + 3]);
            uint2 o;
            o.x = *(uint32_t*)&a;
            o.y = *(uint32_t*)&c;
            *(uint2*)(g_nhwc + off + ((size_t)b * HW + hwbase + rep * 32 + cr) * NCH + c0 + f4 * 4) = o;
        }
}

// ---------------------------------------------------------------------------
// ROIAlign from fp16 NHWC: 32 channel-octets (16B LDG = 8 fp16 ch) x 8
// bin-groups. Warp = one full 512B pixel row -> coalesced. fp32 math.
// ---------------------------------------------------------------------------
__device__ __forceinline__ void acc8(float* acc, uint4 v, float w) {
    half2* h = (half2*)&v;
#pragma unroll
    for (int e = 0; e < 4; e++) {
        float2 f = __half22float2(h[e]);
        acc[2 * e]     += w * f.x;
        acc[2 * e + 1] += w * f.y;
    }
}

__global__ void roi_align_kernel(const float* __restrict__ rois) {
    extern __shared__ float shbuf[];  // 12544 floats, [channel*49 + bin]
    __shared__ int   s_ix0[14], s_ix1[14], s_iy0[14], s_iy1[14];
    __shared__ float s_wx0[14], s_wx1[14], s_wy0[14], s_wy1[14];

    int n = blockIdx.x;
    int tid = threadIdx.x;
    int c8  = tid & 31;   // channel octet 0..31
    int grp = tid >> 5;   // 0..7

    const float* r = rois + (size_t)n * 5;
    int   b  = (int)r[0];
    float x1 = r[1], y1 = r[2], x2 = r[3], y2 = r[4];

    float w = x2 - x1, h = y2 - y1;
    float kf = floorf(4.0f + log2f(sqrtf(fmaxf(w * h, 1e-6f)) / 224.0f));
    kf = fminf(fmaxf(kf, 2.0f), 5.0f);
    int lvl = (int)kf - 2;

    float stride = (float)(4 << lvl);
    int H = 768 >> (lvl + 2);
    int W = 1280 >> (lvl + 2);
    const uint4* base4 = (const uint4*)(g_nhwc + c_lvl_off[lvl] + (size_t)b * H * W * NCH);

    if (tid < 28) {
        bool isx = tid < 14;
        int  s   = isx ? tid : tid - 14;
        float lo = isx ? x1 : y1;
        float hi = isx ? x2 : y2;
        int size = isx ? W : H;
        float a = lo / stride - 0.5f;
        float bb = hi / stride - 0.5f;
        float coord = a + (bb - a) * (((float)s + 0.5f) / 14.0f);
        float valid = (coord > -1.0f && coord < (float)size) ? 1.0f : 0.0f;
        float cc = fminf(fmaxf(coord, 0.0f), (float)(size - 1));
        int i0 = (int)floorf(cc);
        int i1 = min(i0 + 1, size - 1);
        float frac = cc - (float)i0;
        if (isx) { s_ix0[s] = i0; s_ix1[s] = i1; s_wx0[s] = (1.0f - frac) * valid; s_wx1[s] = frac * valid; }
        else     { s_iy0[s] = i0; s_iy1[s] = i1; s_wy0[s] = (1.0f - frac) * valid; s_wy1[s] = frac * valid; }
    }
    __syncthreads();

    for (int bin = grp; bin < 49; bin += 8) {
        int by = bin / 7, bx = bin - by * 7;
        float acc[8] = {};
#pragma unroll
        for (int i = 0; i < 2; i++) {
            int sy = by * 2 + i;
            float wy0 = s_wy0[sy], wy1 = s_wy1[sy];
            int row0 = s_iy0[sy] * W;
            int row1 = s_iy1[sy] * W;
#pragma unroll
            for (int j = 0; j < 2; j++) {
                int sx = bx * 2 + j;
                float wx0 = s_wx0[sx], wx1 = s_wx1[sx];
                int xa = s_ix0[sx], xb = s_ix1[sx];
                uint4 v00 = __ldg(base4 + (size_t)(row0 + xa) * 32 + c8);
                uint4 v01 = __ldg(base4 + (size_t)(row0 + xb) * 32 + c8);
                uint4 v10 = __ldg(base4 + (size_t)(row1 + xa) * 32 + c8);
                uint4 v11 = __ldg(base4 + (size_t)(row1 + xb) * 32 + c8);
                acc8(acc, v00, wy0 * wx0);
                acc8(acc, v01, wy0 * wx1);
                acc8(acc, v10, wy1 * wx0);
                acc8(acc, v11, wy1 * wx1);
            }
        }
        int ch = c8 * 8;
#pragma unroll
        for (int e = 0; e < 8; e++)
            shbuf[(ch + e) * 49 + bin] = acc[e] * 0.25f;
    }
    __syncthreads();

    uint32_t* hd = (uint32_t*)(g_p5_hi + (size_t)n * 12544);
    uint32_t* ld = (uint32_t*)(g_p5_lo + (size_t)n * 12544);
    for (int i = tid; i < 6272; i += 256) {
        float v0 = shbuf[2 * i], v1 = shbuf[2 * i + 1];
        uint32_t hh, ll;
        pack_hi_lo(v0, v1, hh, ll);
        hd[i] = hh; ld[i] = ll;
    }
}

// ---------------------------------------------------------------------------
// fp32 -> bf16 hi/lo split (for weights)
// ---------------------------------------------------------------------------
__global__ void split_kernel(const float* __restrict__ in,
                             __nv_bfloat16* __restrict__ hi,
                             __nv_bfloat16* __restrict__ lo, int n4) {
    int i = blockIdx.x * blockDim.x + threadIdx.x;
    if (i >= n4) return;
    float4 v = ((const float4*)in)[i];
    uint32_t h0, h1, l0, l1;
    pack_hi_lo(v.x, v.y, h0, l0);
    pack_hi_lo(v.z, v.w, h1, l1);
    ((uint2*)hi)[i] = make_uint2(h0, h1);
    ((uint2*)lo)[i] = make_uint2(l0, l1);
}

// ---------------------------------------------------------------------------
// GEMM: C[M,N] = A[M,K] @ B[N,K]^T + bias, ReLU.
// sm_103a: tcgen05, D = Ah*Bh + Ah*Bl + Al*Bh, fp32 TMEM accumulation.
// 128x128 tile, BK=64, 256 threads, cp.async 3-stage pipeline with lagged
// MMA-completion wait.
// ---------------------------------------------------------------------------
__device__ __forceinline__ void load_tile16(uint32_t s_tile, const __nv_bfloat16* g,
                                            int ldK, int tid) {
#pragma unroll
    for (int q = 0; q < 4; q++) {
        int gid = tid + q * 256;
        int row = gid >> 3, c16 = gid & 7;
        uint32_t dst = s_tile + row * 128 + ((c16 ^ (row & 7)) << 4);
        const char* src = (const char*)(g + (size_t)row * ldK) + (c16 << 4);
        asm volatile("cp.async.cg.shared.global [%0], [%1], 16;" :: "r"(dst), "l"(src) : "memory");
    }
}

template <bool SPLIT_OUT>
__global__ __launch_bounds__(256, 1) void gemm_tc(
    const __nv_bfloat16* __restrict__ Ahi, const __nv_bfloat16* __restrict__ Alo,
    const __nv_bfloat16* __restrict__ Bhi, const __nv_bfloat16* __restrict__ Blo,
    const float* __restrict__ bias,
    float* __restrict__ Cf, __nv_bfloat16* __restrict__ Chi, __nv_bfloat16* __restrict__ Clo,
    int N, int K) {
    extern __shared__ char dsm[];
    int tid = threadIdx.x;
    int bm = blockIdx.y * 128, bn = blockIdx.x * 128;

#if HAS_TCGEN05
    __shared__ uint32_t s_tmem;
    __shared__ uint64_t s_mbar[3];

    uint32_t sbase = (smem_u32(dsm) + 1023u) & ~1023u;
    int wid = tid >> 5, lid = tid & 31;

    uint32_t mb[3] = { smem_u32(&s_mbar[0]), smem_u32(&s_mbar[1]), smem_u32(&s_mbar[2]) };

    if (wid == 0) TCGEN05_ALLOC(smem_u32(&s_tmem), 128);
    if (tid == 0) { MBARRIER_INIT(mb[0], 1); MBARRIER_INIT(mb[1], 1); MBARRIER_INIT(mb[2], 1); }
    __syncthreads();
    uint32_t tmem = s_tmem;
    if (wid == 0) TCGEN05_RELINQ();

    const int nblk = K >> 6;

    const __nv_bfloat16* Ah = Ahi + (size_t)bm * K;
    const __nv_bfloat16* Al = Alo + (size_t)bm * K;
    const __nv_bfloat16* Bh = Bhi + (size_t)bn * K;
    const __nv_bfloat16* Bl = Blo + (size_t)bn * K;

#pragma unroll
    for (int p = 0; p < 2; p++) {
        uint32_t st = sbase + (uint32_t)p * 65536u;
        load_tile16(st,          Ah + p * 64, K, tid);
        load_tile16(st + 16384u, Al + p * 64, K, tid);
        load_tile16(st + 32768u, Bh + p * 64, K, tid);
        load_tile16(st + 49152u, Bl + p * 64, K, tid);
        CP_COMMIT();
    }

    int ph[3] = {0, 0, 0};
    int s = 0, sp = 2;
    for (int i = 0; i < nblk; i++) {
        CP_WAIT_1();
        __syncthreads();
        if (tid < 32) {
            if (elect_one()) {
                FENCE_PROXY_ASYNC();
                uint32_t st = sbase + (uint32_t)s * 65536u;
                uint64_t dah = MAKE_DESC(st);
                uint64_t dal = MAKE_DESC(st + 16384u);
                uint64_t dbh = MAKE_DESC(st + 32768u);
                uint64_t dbl = MAKE_DESC(st + 49152u);
                bool en = (i > 0);
#pragma unroll
                for (int k = 0; k < 4; k++) {
                    mma_f16_ss(tmem, dah + k * 2, dbh + k * 2, GEMM_IDESC, en); en = true;
                    mma_f16_ss(tmem, dah + k * 2, dbl + k * 2, GEMM_IDESC, true);
                    mma_f16_ss(tmem, dal + k * 2, dbh + k * 2, GEMM_IDESC, true);
                }
                TCGEN05_COMMIT(mb[s]);
            }
        }
        if (i >= 1) {
            MBARRIER_WAIT_PARITY(mb[sp], ph[sp]);
            ph[sp] ^= 1;
            if (i + 2 < nblk) {
                uint32_t st = sbase + (uint32_t)sp * 65536u;
                int j = i + 2;
                load_tile16(st,          Ah + j * 64, K, tid);
                load_tile16(st + 16384u, Al + j * 64, K, tid);
                load_tile16(st + 32768u, Bh + j * 64, K, tid);
                load_tile16(st + 49152u, Bl + j * 64, K, tid);
            }
        } else if (nblk > 2) {
            uint32_t st = sbase + 2u * 65536u;
            load_tile16(st,          Ah + 2 * 64, K, tid);
            load_tile16(st + 16384u, Al + 2 * 64, K, tid);
            load_tile16(st + 32768u, Bh + 2 * 64, K, tid);
            load_tile16(st + 49152u, Bl + 2 * 64, K, tid);
        }
        CP_COMMIT();
        sp = s;
        s = (s == 2) ? 0 : s + 1;
    }

    {
        int lastS = (nblk - 1) % 3;
        MBARRIER_WAIT_PARITY(mb[lastS], ph[lastS]);
    }
    TCGEN05_FENCE_AFTER();

    if (tid < 128) {
        int row = bm + wid * 32 + lid;
#pragma unroll
        for (int cb = 0; cb < 128; cb += 32) {
            uint32_t rr[32];
            TCGEN05_LD_X32(rr, tmem + cb);
            TCGEN05_WAIT_LD();
            if (SPLIT_OUT) {
                uint32_t* hd = (uint32_t*)(Chi + (size_t)row * N + bn + cb);
                uint32_t* ld = (uint32_t*)(Clo + (size_t)row * N + bn + cb);
#pragma unroll
                for (int c = 0; c < 32; c += 2) {
                    float v0 = fmaxf(__uint_as_float(rr[c])     + bias[bn + cb + c],     0.0f);
                    float v1 = fmaxf(__uint_as_float(rr[c + 1]) + bias[bn + cb + c + 1], 0.0f);
                    uint32_t hh, ll;
                    pack_hi_lo(v0, v1, hh, ll);
                    hd[c >> 1] = hh; ld[c >> 1] = ll;
                }
            } else {
                float* cd = Cf + (size_t)row * N + bn + cb;
#pragma unroll
                for (int c = 0; c < 32; c++)
                    cd[c] = fmaxf(__uint_as_float(rr[c]) + bias[bn + cb + c], 0.0f);
            }
        }
        TCGEN05_FENCE_BEFORE();
    }
    __syncthreads();
    if (wid == 0) TCGEN05_DEALLOC(tmem, 128);

#else  // ---------------- SIMT fallback (baseline compute_103 pass) ---------
    float* As = (float*)dsm;
    float* Bs = As + 16 * 132;

    int tr = (tid >> 4) * 8;
    int tc = (tid & 15) * 8;

    float acc[8][8] = {};

    for (int k0 = 0; k0 < K; k0 += 16) {
#pragma unroll
        for (int e = 0; e < 8; e++) {
            int idx = tid * 8 + e;
            int kk = idx >> 7, rr = idx & 127;
            As[kk * 132 + rr] = __bfloat162float(Ahi[(size_t)(bm + rr) * K + k0 + kk]) +
                                __bfloat162float(Alo[(size_t)(bm + rr) * K + k0 + kk]);
            Bs[kk * 132 + rr] = __bfloat162float(Bhi[(size_t)(bn + rr) * K + k0 + kk]) +
                                __bfloat162float(Blo[(size_t)(bn + rr) * K + k0 + kk]);
        }
        __syncthreads();
#pragma unroll
        for (int k = 0; k < 16; k++) {
            float ra[8], rb[8];
#pragma unroll
            for (int i = 0; i < 8; i++) ra[i] = As[k * 132 + tr + i];
#pragma unroll
            for (int j = 0; j < 8; j++) rb[j] = Bs[k * 132 + tc + j];
#pragma unroll
            for (int i = 0; i < 8; i++)
#pragma unroll
                for (int j = 0; j < 8; j++) acc[i][j] += ra[i] * rb[j];
        }
        __syncthreads();
    }

#pragma unroll
    for (int i = 0; i < 8; i++) {
#pragma unroll
        for (int j = 0; j < 8; j += 2) {
            float v0 = fmaxf(acc[i][j]     + bias[bn + tc + j],     0.0f);
            float v1 = fmaxf(acc[i][j + 1] + bias[bn + tc + j + 1], 0.0f);
            size_t o = (size_t)(bm + tr + i) * N + bn + tc + j;
            if (SPLIT_OUT) {
                uint32_t hh, ll;
                pack_hi_lo(v0, v1, hh, ll);
                *(uint32_t*)(Chi + o) = hh;
                *(uint32_t*)(Clo + o) = ll;
            } else {
                Cf[o] = v0; Cf[o + 1] = v1;
            }
        }
    }
#endif
}

// ---------------------------------------------------------------------------
// Final projection: out[n, j] = dot(fc2[n,:], p_w[j,:]) + p_b[j], j < 20
// ---------------------------------------------------------------------------
__global__ void proj_kernel(const float* __restrict__ fc2,
                            const float* __restrict__ p_w,
                            const float* __restrict__ p_b,
                            float* __restrict__ out, int NJ) {
    __shared__ float sh[1024];
    int n = blockIdx.x;
    for (int i = threadIdx.x; i < 1024; i += blockDim.x)
        sh[i] = fc2[(size_t)n * 1024 + i];
    __syncthreads();
    int j = threadIdx.x;
    if (j < NJ) {
        const float* wrow = p_w + (size_t)j * 1024;
        float s = p_b[j];
#pragma unroll 8
        for (int k = 0; k < 1024; k++) s += sh[k] * wrow[k];
        out[(size_t)n * NJ + j] = s;
    }
}

// ---------------------------------------------------------------------------
extern "C" void kernel_launch(void* const* d_in, const int* in_sizes, int n_in,
                              void* d_out, int out_size) {
    const float* fm0   = (const float*)d_in[0];
    const float* fm1   = (const float*)d_in[1];
    const float* fm2   = (const float*)d_in[2];
    const float* fm3   = (const float*)d_in[3];
    const float* rois  = (const float*)d_in[4];
    const float* fc1_w = (const float*)d_in[5];
    const float* fc1_b = (const float*)d_in[6];
    const float* fc2_w = (const float*)d_in[7];
    const float* fc2_b = (const float*)d_in[8];
    const float* p_w   = (const float*)d_in[9];
    const float* p_b   = (const float*)d_in[10];
    float* out = (float*)d_out;

    int nrois = in_sizes[4] / 5;   // 1024
    int nj = out_size / nrois;     // 20

    static cudaStream_t s2 = nullptr;
    static cudaEvent_t evF = nullptr, evJ = nullptr;
    if (!s2) {
        cudaStreamCreateWithFlags(&s2, cudaStreamNonBlocking);
        cudaEventCreateWithFlags(&evF, cudaEventDisableTiming);
        cudaEventCreateWithFlags(&evJ, cudaEventDisableTiming);
    }

    __nv_bfloat16 *w1h, *w1l, *w2h, *w2l, *p5h, *p5l, *f1h, *f1l;
    float* fc2p;
    cudaGetSymbolAddress((void**)&w1h, g_w1_hi);
    cudaGetSymbolAddress((void**)&w1l, g_w1_lo);
    cudaGetSymbolAddress((void**)&w2h, g_w2_hi);
    cudaGetSymbolAddress((void**)&w2l, g_w2_lo);
    cudaGetSymbolAddress((void**)&p5h, g_p5_hi);
    cudaGetSymbolAddress((void**)&p5l, g_p5_lo);
    cudaGetSymbolAddress((void**)&f1h, g_fc1_hi);
    cudaGetSymbolAddress((void**)&f1l, g_fc1_lo);
    cudaGetSymbolAddress((void**)&fc2p, g_fc2);

    // Fork: weight splits run concurrent with transposes + ROI.
    cudaEventRecord(evF, 0);
    cudaStreamWaitEvent(s2, evF, 0);
    split_kernel<<<(12544 * 1024 / 4 + 255) / 256, 256, 0, s2>>>(fc1_w, w1h, w1l, 12544 * 1024 / 4);
    split_kernel<<<(1024 * 1024 / 4 + 255) / 256, 256, 0, s2>>>(fc2_w, w2h, w2l, 1024 * 1024 / 4);
    cudaEventRecord(evJ, s2);

    // Main: NCHW fp32 -> NHWC fp16 (8 tiles/block, MLP=8), then ROIAlign.
    nchw2nhwc_kernel<<<dim3((61440 / 32 + 7) / 8, 8, 2), 256>>>(fm0, 61440, (size_t)0);
    nchw2nhwc_kernel<<<dim3((15360 / 32 + 7) / 8, 8, 2), 256>>>(fm1, 15360, (size_t)31457280);
    nchw2nhwc_kernel<<<dim3((3840 / 32 + 7) / 8, 8, 2), 256>>>(fm2, 3840, (size_t)39321600);
    nchw2nhwc_kernel<<<dim3((960 / 32 + 7) / 8, 8, 2), 256>>>(fm3, 960, (size_t)41287680);

    cudaFuncSetAttribute(roi_align_kernel,
                         cudaFuncAttributeMaxDynamicSharedMemorySize, 50176);
    roi_align_kernel<<<nrois, 256, 50176>>>(rois);

    cudaStreamWaitEvent(0, evJ, 0);

    const int GEMM_SMEM = 1024 + 3 * 65536;  // 197632 (3-stage)
    cudaFuncSetAttribute(gemm_tc<true>,
                         cudaFuncAttributeMaxDynamicSharedMemorySize, GEMM_SMEM);
    cudaFuncSetAttribute(gemm_tc<false>,
                         cudaFuncAttributeMaxDynamicSharedMemorySize, GEMM_SMEM);

    // FC1: [1024, 12544] x [1024, 12544]^T -> fc1 hi/lo
    gemm_tc<true><<<dim3(8, nrois / 128), 256, GEMM_SMEM>>>(
        p5h, p5l, w1h, w1l, fc1_b, nullptr, f1h, f1l, 1024, 12544);
    // FC2: [1024, 1024] x [1024, 1024]^T -> fc2 fp32
    gemm_tc<false><<<dim3(8, nrois / 128), 256, GEMM_SMEM>>>(
        f1h, f1l, w2h, w2l, fc2_b, fc2p, nullptr, nullptr, 1024, 1024);

    // Projection
    proj_kernel<<<nrois, 256>>>(fc2p, p_w, p_b, out, nj);
}

// round 9
// speedup vs baseline: 1.5336x; 1.1891x over previous
#include <cuda_runtime.h>
#include <cuda_bf16.h>
#include <cuda_fp16.h>
#include <cstdint>

// ---------------------------------------------------------------------------
// Shapes: B=2, C=256, Im 768x1280, strides {4,8,16,32}, N=1024 rois
// pool5 D = 256*49 = 12544; fc1: 12544->1024 relu; fc2: 1024->1024 relu; proj->20
// ---------------------------------------------------------------------------

#define NCH 256

#if defined(__CUDA_ARCH__) && defined(__CUDA_ARCH_FEAT_SM103_ALL)
#define HAS_TCGEN05 1
#else
#define HAS_TCGEN05 0
#endif

__device__ __half g_nhwc[41779200];          // fp16 NHWC staging
__device__ __nv_bfloat16 g_p5_hi[1024 * 12544];
__device__ __nv_bfloat16 g_p5_lo[1024 * 12544];
__device__ __nv_bfloat16 g_w1_hi[1024 * 12544];
__device__ __nv_bfloat16 g_w1_lo[1024 * 12544];
__device__ __nv_bfloat16 g_fc1_hi[1024 * 1024];
__device__ __nv_bfloat16 g_fc1_lo[1024 * 1024];
__device__ __nv_bfloat16 g_w2_hi[1024 * 1024];
__device__ __nv_bfloat16 g_w2_lo[1024 * 1024];
__device__ float g_fc2[1024 * 1024];
__device__ float g_part[2 * 1024 * 1024];    // split-K partials for FC1

__constant__ size_t c_lvl_off[4] = {0, 31457280, 39321600, 41287680};

// ============================ PTX helpers ==================================
__device__ __forceinline__ uint32_t smem_u32(const void* p) {
    uint32_t a;
    asm("{ .reg .u64 t; cvta.to.shared.u64 t, %1; cvt.u32.u64 %0, t; }" : "=r"(a) : "l"(p));
    return a;
}
__device__ __forceinline__ uint32_t elect_one() {
    uint32_t p;
    asm volatile("{\n\t.reg .pred p;\n\telect.sync _|p, 0xFFFFFFFF;\n\tselp.b32 %0, 1, 0, p;\n\t}" : "=r"(p));
    return p;
}
#define MBARRIER_INIT(addr, cnt) \
    asm volatile("mbarrier.init.shared.b64 [%0], %1;" :: "r"(addr), "r"(cnt) : "memory")
#define MBARRIER_WAIT_PARITY(addr, par) do {                                          \
    uint32_t _m = (addr); uint32_t _p = (par); uint32_t _d;                           \
    asm volatile("{\n\t.reg .pred p;\n\t"                                             \
        "mbarrier.try_wait.parity.acquire.cta.shared::cta.b64 p, [%1], %2;\n\t"       \
        "selp.b32 %0, 1, 0, p;\n\t}" : "=r"(_d) : "r"(_m), "r"(_p) : "memory");       \
    if (!_d) {                                                                        \
        asm volatile("{\n\t.reg .pred P1;\n\t"                                        \
            "WL_%=:\n\t"                                                              \
            "mbarrier.try_wait.parity.acquire.cta.shared::cta.b64 P1, [%0], %1, 0x989680;\n\t" \
            "@P1 bra.uni WD_%=;\n\tbra.uni WL_%=;\n\tWD_%=:\n\t}"                     \
            :: "r"(_m), "r"(_p) : "memory");                                          \
    } } while (0)
#define FENCE_PROXY_ASYNC() asm volatile("fence.proxy.async.shared::cta;" ::: "memory")
#define CP_COMMIT() asm volatile("cp.async.commit_group;" ::: "memory")
#define CP_WAIT_1() asm volatile("cp.async.wait_group 1;" ::: "memory")

#if HAS_TCGEN05
#define TCGEN05_ALLOC(sa, n) \
    asm volatile("tcgen05.alloc.cta_group::1.sync.aligned.shared::cta.b32 [%0], %1;" :: "r"(sa), "r"(n) : "memory")
#define TCGEN05_DEALLOC(t, n) \
    asm volatile("tcgen05.dealloc.cta_group::1.sync.aligned.b32 %0, %1;" :: "r"(t), "r"(n))
#define TCGEN05_RELINQ() \
    asm volatile("tcgen05.relinquish_alloc_permit.cta_group::1.sync.aligned;")
#define TCGEN05_COMMIT(mb) \
    asm volatile("tcgen05.commit.cta_group::1.mbarrier::arrive::one.shared::cluster.b64 [%0];" :: "r"(mb) : "memory")
#define TCGEN05_FENCE_AFTER()  asm volatile("tcgen05.fence::after_thread_sync;" ::: "memory")
#define TCGEN05_FENCE_BEFORE() asm volatile("tcgen05.fence::before_thread_sync;" ::: "memory")
#define TCGEN05_WAIT_LD() asm volatile("tcgen05.wait::ld.sync.aligned;" ::: "memory")

#define TCGEN05_LD_X32(r, ta)                                                          \
    asm volatile("tcgen05.ld.sync.aligned.32x32b.x32.b32 "                             \
        "{%0, %1, %2, %3, %4, %5, %6, %7, %8, %9, %10, %11, %12, %13, %14, %15, "      \
        " %16, %17, %18, %19, %20, %21, %22, %23, %24, %25, %26, %27, %28, %29, %30, %31}, [%32];" \
        : "=r"((r)[0]), "=r"((r)[1]), "=r"((r)[2]), "=r"((r)[3]),                      \
          "=r"((r)[4]), "=r"((r)[5]), "=r"((r)[6]), "=r"((r)[7]),                      \
          "=r"((r)[8]), "=r"((r)[9]), "=r"((r)[10]), "=r"((r)[11]),                    \
          "=r"((r)[12]), "=r"((r)[13]), "=r"((r)[14]), "=r"((r)[15]),                  \
          "=r"((r)[16]), "=r"((r)[17]), "=r"((r)[18]), "=r"((r)[19]),                  \
          "=r"((r)[20]), "=r"((r)[21]), "=r"((r)[22]), "=r"((r)[23]),                  \
          "=r"((r)[24]), "=r"((r)[25]), "=r"((r)[26]), "=r"((r)[27]),                  \
          "=r"((r)[28]), "=r"((r)[29]), "=r"((r)[30]), "=r"((r)[31])                   \
        : "r"(ta))

__device__ __forceinline__ void mma_f16_ss(uint32_t d, uint64_t a, uint64_t b,
                                           uint32_t idesc, bool en) {
    uint32_t e = en ? 1u : 0u;
    asm volatile(
        "{\n\t.reg .pred p;\n\tsetp.ne.u32 p, %4, 0;\n\t"
        "tcgen05.mma.cta_group::1.kind::f16 [%0], %1, %2, %3, {%5, %5, %5, %5}, p;\n\t}"
        :: "r"(d), "l"(a), "l"(b), "r"(idesc), "r"(e), "r"(0u) : "memory");
}
#endif  // HAS_TCGEN05

// SW128 K-major descriptor: layout=2, version=1, SBO=64, LBO=1
static constexpr uint64_t DESC_BASE_SW128 =
    (uint64_t(2) << 61) | (uint64_t(1) << 46) | (uint64_t(64) << 32) | (uint64_t(1) << 16);
#define MAKE_DESC(a) (DESC_BASE_SW128 | ((uint64_t)((a) >> 4) & 0x3FFF))

// idesc kind::f16: F32 accum, BF16 a/b, M=128, N=128
static constexpr uint32_t GEMM_IDESC =
    (1u << 4) | (1u << 7) | (1u << 10) | ((128u / 8u) << 17) | ((128u / 16u) << 24);

__device__ __forceinline__ void pack_hi_lo(float v0, float v1, uint32_t& h, uint32_t& l) {
    asm("cvt.rn.bf16x2.f32 %0, %1, %2;" : "=r"(h) : "f"(v1), "f"(v0));
    float l0 = v0 - __uint_as_float(h << 16);
    float l1 = v1 - __uint_as_float(h & 0xffff0000u);
    asm("cvt.rn.bf16x2.f32 %0, %1, %2;" : "=r"(l) : "f"(l1), "f"(l0));
}

// ---------------------------------------------------------------------------
// NCHW fp32 -> NHWC fp16: 8 tiles (32C x 32HW)/block, MLP=8, fp16 stores.
// ---------------------------------------------------------------------------
__global__ void nchw2nhwc_kernel(const float* __restrict__ in, int HW, size_t off) {
    __shared__ float tile[8][32][33];
    int b = blockIdx.z;
    int c0 = blockIdx.y * 32;
    int t = threadIdx.x;            // 256
    int cr  = t >> 3;               // 0..31
    int f4  = t & 7;                // 0..7

    int hwbase = blockIdx.x * 256;
    int nrep = (HW - hwbase + 31) >> 5;      // uniform; 1..8
    if (nrep > 8) nrep = 8;

    float4 v[8];
#pragma unroll
    for (int rep = 0; rep < 8; rep++)
        if (rep < nrep)
            v[rep] = *((const float4*)(in + ((size_t)b * NCH + c0 + cr) * HW + hwbase + rep * 32) + f4);

#pragma unroll
    for (int rep = 0; rep < 8; rep++)
        if (rep < nrep) {
            tile[rep][f4 * 4 + 0][cr] = v[rep].x;
            tile[rep][f4 * 4 + 1][cr] = v[rep].y;
            tile[rep][f4 * 4 + 2][cr] = v[rep].z;
            tile[rep][f4 * 4 + 3][cr] = v[rep].w;
        }
    __syncthreads();

#pragma unroll
    for (int rep = 0; rep < 8; rep++)
        if (rep < nrep) {
            half2 a = __floats2half2_rn(tile[rep][cr][f4 * 4 + 0], tile[rep][cr][f4 * 4 + 1]);
            half2 c = __floats2half2_rn(tile[rep][cr][f4 * 4 + 2], tile[rep][cr][f4 * 4 + 3]);
            uint2 o;
            o.x = *(uint32_t*)&a;
            o.y = *(uint32_t*)&c;
            *(uint2*)(g_nhwc + off + ((size_t)b * HW + hwbase + rep * 32 + cr) * NCH + c0 + f4 * 4) = o;
        }
}

// ---------------------------------------------------------------------------
// ROIAlign from fp16 NHWC: 32 channel-octets x 8 bin-groups, fp32 math.
// ---------------------------------------------------------------------------
__device__ __forceinline__ void acc8(float* acc, uint4 v, float w) {
    half2* h = (half2*)&v;
#pragma unroll
    for (int e = 0; e < 4; e++) {
        float2 f = __half22float2(h[e]);
        acc[2 * e]     += w * f.x;
        acc[2 * e + 1] += w * f.y;
    }
}

__global__ void roi_align_kernel(const float* __restrict__ rois) {
    extern __shared__ float shbuf[];  // 12544 floats, [channel*49 + bin]
    __shared__ int   s_ix0[14], s_ix1[14], s_iy0[14], s_iy1[14];
    __shared__ float s_wx0[14], s_wx1[14], s_wy0[14], s_wy1[14];

    int n = blockIdx.x;
    int tid = threadIdx.x;
    int c8  = tid & 31;   // channel octet 0..31
    int grp = tid >> 5;   // 0..7

    const float* r = rois + (size_t)n * 5;
    int   b  = (int)r[0];
    float x1 = r[1], y1 = r[2], x2 = r[3], y2 = r[4];

    float w = x2 - x1, h = y2 - y1;
    float kf = floorf(4.0f + log2f(sqrtf(fmaxf(w * h, 1e-6f)) / 224.0f));
    kf = fminf(fmaxf(kf, 2.0f), 5.0f);
    int lvl = (int)kf - 2;

    float stride = (float)(4 << lvl);
    int H = 768 >> (lvl + 2);
    int W = 1280 >> (lvl + 2);
    const uint4* base4 = (const uint4*)(g_nhwc + c_lvl_off[lvl] + (size_t)b * H * W * NCH);

    if (tid < 28) {
        bool isx = tid < 14;
        int  s   = isx ? tid : tid - 14;
        float lo = isx ? x1 : y1;
        float hi = isx ? x2 : y2;
        int size = isx ? W : H;
        float a = lo / stride - 0.5f;
        float bb = hi / stride - 0.5f;
        float coord = a + (bb - a) * (((float)s + 0.5f) / 14.0f);
        float valid = (coord > -1.0f && coord < (float)size) ? 1.0f : 0.0f;
        float cc = fminf(fmaxf(coord, 0.0f), (float)(size - 1));
        int i0 = (int)floorf(cc);
        int i1 = min(i0 + 1, size - 1);
        float frac = cc - (float)i0;
        if (isx) { s_ix0[s] = i0; s_ix1[s] = i1; s_wx0[s] = (1.0f - frac) * valid; s_wx1[s] = frac * valid; }
        else     { s_iy0[s] = i0; s_iy1[s] = i1; s_wy0[s] = (1.0f - frac) * valid; s_wy1[s] = frac * valid; }
    }
    __syncthreads();

    for (int bin = grp; bin < 49; bin += 8) {
        int by = bin / 7, bx = bin - by * 7;
        float acc[8] = {};
#pragma unroll
        for (int i = 0; i < 2; i++) {
            int sy = by * 2 + i;
            float wy0 = s_wy0[sy], wy1 = s_wy1[sy];
            int row0 = s_iy0[sy] * W;
            int row1 = s_iy1[sy] * W;
#pragma unroll
            for (int j = 0; j < 2; j++) {
                int sx = bx * 2 + j;
                float wx0 = s_wx0[sx], wx1 = s_wx1[sx];
                int xa = s_ix0[sx], xb = s_ix1[sx];
                uint4 v00 = __ldg(base4 + (size_t)(row0 + xa) * 32 + c8);
                uint4 v01 = __ldg(base4 + (size_t)(row0 + xb) * 32 + c8);
                uint4 v10 = __ldg(base4 + (size_t)(row1 + xa) * 32 + c8);
                uint4 v11 = __ldg(base4 + (size_t)(row1 + xb) * 32 + c8);
                acc8(acc, v00, wy0 * wx0);
                acc8(acc, v01, wy0 * wx1);
                acc8(acc, v10, wy1 * wx0);
                acc8(acc, v11, wy1 * wx1);
            }
        }
        int ch = c8 * 8;
#pragma unroll
        for (int e = 0; e < 8; e++)
            shbuf[(ch + e) * 49 + bin] = acc[e] * 0.25f;
    }
    __syncthreads();

    uint32_t* hd = (uint32_t*)(g_p5_hi + (size_t)n * 12544);
    uint32_t* ld = (uint32_t*)(g_p5_lo + (size_t)n * 12544);
    for (int i = tid; i < 6272; i += 256) {
        float v0 = shbuf[2 * i], v1 = shbuf[2 * i + 1];
        uint32_t hh, ll;
        pack_hi_lo(v0, v1, hh, ll);
        hd[i] = hh; ld[i] = ll;
    }
}

// ---------------------------------------------------------------------------
// fp32 -> bf16 hi/lo split (for weights)
// ---------------------------------------------------------------------------
__global__ void split_kernel(const float* __restrict__ in,
                             __nv_bfloat16* __restrict__ hi,
                             __nv_bfloat16* __restrict__ lo, int n4) {
    int i = blockIdx.x * blockDim.x + threadIdx.x;
    if (i >= n4) return;
    float4 v = ((const float4*)in)[i];
    uint32_t h0, h1, l0, l1;
    pack_hi_lo(v.x, v.y, h0, l0);
    pack_hi_lo(v.z, v.w, h1, l1);
    ((uint2*)hi)[i] = make_uint2(h0, h1);
    ((uint2*)lo)[i] = make_uint2(l0, l1);
}

// ---------------------------------------------------------------------------
// Split-K reduce: out = relu(p0 + p1 + bias), packed to bf16 hi/lo.
// 1024x1024 elems as float4; bias per column.
// ---------------------------------------------------------------------------
__global__ void reduce_split_kernel(const float* __restrict__ part,
                                    const float* __restrict__ bias,
                                    __nv_bfloat16* __restrict__ hi,
                                    __nv_bfloat16* __restrict__ lo) {
    int i = blockIdx.x * 256 + threadIdx.x;   // float4 index, 262144 total
    float4 a = ((const float4*)part)[i];
    float4 b = ((const float4*)(part + 1048576))[i];
    float4 bs = ((const float4*)bias)[i & 255];
    float v0 = fmaxf(a.x + b.x + bs.x, 0.0f);
    float v1 = fmaxf(a.y + b.y + bs.y, 0.0f);
    float v2 = fmaxf(a.z + b.z + bs.z, 0.0f);
    float v3 = fmaxf(a.w + b.w + bs.w, 0.0f);
    uint32_t h0, h1, l0, l1;
    pack_hi_lo(v0, v1, h0, l0);
    pack_hi_lo(v2, v3, h1, l1);
    ((uint2*)hi)[i] = make_uint2(h0, h1);
    ((uint2*)lo)[i] = make_uint2(l0, l1);
}

// ---------------------------------------------------------------------------
// GEMM: C[M,N] = A[M,K] @ B[N,K]^T, tcgen05 hi/lo bf16, 128x128 tile, BK=64,
// 3-stage cp.async pipeline. blockIdx.z = split-K slice (A/B advance z*K
// along a row of leading dim ldK; C advances z*M*N).
// MODE: 0 = fp32 out + bias + relu, 2 = raw fp32 out (split-K partial).
// ---------------------------------------------------------------------------
__device__ __forceinline__ void load_tile16(uint32_t s_tile, const __nv_bfloat16* g,
                                            int ldK, int tid) {
#pragma unroll
    for (int q = 0; q < 4; q++) {
        int gid = tid + q * 256;
        int row = gid >> 3, c16 = gid & 7;
        uint32_t dst = s_tile + row * 128 + ((c16 ^ (row & 7)) << 4);
        const char* src = (const char*)(g + (size_t)row * ldK) + (c16 << 4);
        asm volatile("cp.async.cg.shared.global [%0], [%1], 16;" :: "r"(dst), "l"(src) : "memory");
    }
}

template <int MODE>
__global__ __launch_bounds__(256, 1) void gemm_tc(
    const __nv_bfloat16* __restrict__ Ahi, const __nv_bfloat16* __restrict__ Alo,
    const __nv_bfloat16* __restrict__ Bhi, const __nv_bfloat16* __restrict__ Blo,
    const float* __restrict__ bias,
    float* __restrict__ Cf,
    int N, int K, int ldK) {
    extern __shared__ char dsm[];
    int tid = threadIdx.x;
    int bm = blockIdx.y * 128, bn = blockIdx.x * 128;
    int z = blockIdx.z;
    size_t koff = (size_t)z * K;

    const __nv_bfloat16* Ah = Ahi + (size_t)bm * ldK + koff;
    const __nv_bfloat16* Al = Alo + (size_t)bm * ldK + koff;
    const __nv_bfloat16* Bh = Bhi + (size_t)bn * ldK + koff;
    const __nv_bfloat16* Bl = Blo + (size_t)bn * ldK + koff;
    float* Cz = Cf + (size_t)z * (size_t)(gridDim.y * 128) * N;

#if HAS_TCGEN05
    __shared__ uint32_t s_tmem;
    __shared__ uint64_t s_mbar[3];

    uint32_t sbase = (smem_u32(dsm) + 1023u) & ~1023u;
    int wid = tid >> 5, lid = tid & 31;

    uint32_t mb[3] = { smem_u32(&s_mbar[0]), smem_u32(&s_mbar[1]), smem_u32(&s_mbar[2]) };

    if (wid == 0) TCGEN05_ALLOC(smem_u32(&s_tmem), 128);
    if (tid == 0) { MBARRIER_INIT(mb[0], 1); MBARRIER_INIT(mb[1], 1); MBARRIER_INIT(mb[2], 1); }
    __syncthreads();
    uint32_t tmem = s_tmem;
    if (wid == 0) TCGEN05_RELINQ();

    const int nblk = K >> 6;

#pragma unroll
    for (int p = 0; p < 2; p++) {
        uint32_t st = sbase + (uint32_t)p * 65536u;
        load_tile16(st,          Ah + p * 64, ldK, tid);
        load_tile16(st + 16384u, Al + p * 64, ldK, tid);
        load_tile16(st + 32768u, Bh + p * 64, ldK, tid);
        load_tile16(st + 49152u, Bl + p * 64, ldK, tid);
        CP_COMMIT();
    }

    int ph[3] = {0, 0, 0};
    int s = 0, sp = 2;
    for (int i = 0; i < nblk; i++) {
        CP_WAIT_1();
        __syncthreads();
        if (tid < 32) {
            if (elect_one()) {
                FENCE_PROXY_ASYNC();
                uint32_t st = sbase + (uint32_t)s * 65536u;
                uint64_t dah = MAKE_DESC(st);
                uint64_t dal = MAKE_DESC(st + 16384u);
                uint64_t dbh = MAKE_DESC(st + 32768u);
                uint64_t dbl = MAKE_DESC(st + 49152u);
                bool en = (i > 0);
#pragma unroll
                for (int k = 0; k < 4; k++) {
                    mma_f16_ss(tmem, dah + k * 2, dbh + k * 2, GEMM_IDESC, en); en = true;
                    mma_f16_ss(tmem, dah + k * 2, dbl + k * 2, GEMM_IDESC, true);
                    mma_f16_ss(tmem, dal + k * 2, dbh + k * 2, GEMM_IDESC, true);
                }
                TCGEN05_COMMIT(mb[s]);
            }
        }
        if (i >= 1) {
            MBARRIER_WAIT_PARITY(mb[sp], ph[sp]);
            ph[sp] ^= 1;
            if (i + 2 < nblk) {
                uint32_t st = sbase + (uint32_t)sp * 65536u;
                int j = i + 2;
                load_tile16(st,          Ah + j * 64, ldK, tid);
                load_tile16(st + 16384u, Al + j * 64, ldK, tid);
                load_tile16(st + 32768u, Bh + j * 64, ldK, tid);
                load_tile16(st + 49152u, Bl + j * 64, ldK, tid);
            }
        } else if (nblk > 2) {
            uint32_t st = sbase + 2u * 65536u;
            load_tile16(st,          Ah + 2 * 64, ldK, tid);
            load_tile16(st + 16384u, Al + 2 * 64, ldK, tid);
            load_tile16(st + 32768u, Bh + 2 * 64, ldK, tid);
            load_tile16(st + 49152u, Bl + 2 * 64, ldK, tid);
        }
        CP_COMMIT();
        sp = s;
        s = (s == 2) ? 0 : s + 1;
    }

    {
        int lastS = (nblk - 1) % 3;
        MBARRIER_WAIT_PARITY(mb[lastS], ph[lastS]);
    }
    TCGEN05_FENCE_AFTER();

    if (tid < 128) {
        int row = bm + wid * 32 + lid;
#pragma unroll
        for (int cb = 0; cb < 128; cb += 32) {
            uint32_t rr[32];
            TCGEN05_LD_X32(rr, tmem + cb);
            TCGEN05_WAIT_LD();
            float* cd = Cz + (size_t)row * N + bn + cb;
#pragma unroll
            for (int c = 0; c < 32; c++) {
                float v = __uint_as_float(rr[c]);
                if (MODE == 0) v = fmaxf(v + bias[bn + cb + c], 0.0f);
                cd[c] = v;
            }
        }
        TCGEN05_FENCE_BEFORE();
    }
    __syncthreads();
    if (wid == 0) TCGEN05_DEALLOC(tmem, 128);

#else  // ---------------- SIMT fallback (baseline compute_103 pass) ---------
    float* As = (float*)dsm;
    float* Bs = As + 16 * 132;

    int tr = (tid >> 4) * 8;
    int tc = (tid & 15) * 8;

    float acc[8][8] = {};

    for (int k0 = 0; k0 < K; k0 += 16) {
#pragma unroll
        for (int e = 0; e < 8; e++) {
            int idx = tid * 8 + e;
            int kk = idx >> 7, rr = idx & 127;
            As[kk * 132 + rr] = __bfloat162float(Ah[(size_t)rr * ldK + k0 + kk]) +
                                __bfloat162float(Al[(size_t)rr * ldK + k0 + kk]);
            Bs[kk * 132 + rr] = __bfloat162float(Bh[(size_t)rr * ldK + k0 + kk]) +
                                __bfloat162float(Bl[(size_t)rr * ldK + k0 + kk]);
        }
        __syncthreads();
#pragma unroll
        for (int k = 0; k < 16; k++) {
            float ra[8], rb[8];
#pragma unroll
            for (int i = 0; i < 8; i++) ra[i] = As[k * 132 + tr + i];
#pragma unroll
            for (int j = 0; j < 8; j++) rb[j] = Bs[k * 132 + tc + j];
#pragma unroll
            for (int i = 0; i < 8; i++)
#pragma unroll
                for (int j = 0; j < 8; j++) acc[i][j] += ra[i] * rb[j];
        }
        __syncthreads();
    }

#pragma unroll
    for (int i = 0; i < 8; i++) {
#pragma unroll
        for (int j = 0; j < 8; j++) {
            float v = acc[i][j];
            if (MODE == 0) v = fmaxf(v + bias[bn + tc + j], 0.0f);
            Cz[(size_t)(bm + tr + i) * N + bn + tc + j] = v;
        }
    }
#endif
}

// ---------------------------------------------------------------------------
// FC2 epilogue split not needed (fp32 out), proj reads fp32.
// Final projection: out[n, j] = dot(fc2[n,:], p_w[j,:]) + p_b[j], j < 20
// ---------------------------------------------------------------------------
__global__ void proj_kernel(const float* __restrict__ fc2,
                            const float* __restrict__ p_w,
                            const float* __restrict__ p_b,
                            float* __restrict__ out, int NJ) {
    __shared__ float sh[1024];
    int n = blockIdx.x;
    for (int i = threadIdx.x; i < 1024; i += blockDim.x)
        sh[i] = fc2[(size_t)n * 1024 + i];
    __syncthreads();
    int j = threadIdx.x;
    if (j < NJ) {
        const float* wrow = p_w + (size_t)j * 1024;
        float s = p_b[j];
#pragma unroll 8
        for (int k = 0; k < 1024; k++) s += sh[k] * wrow[k];
        out[(size_t)n * NJ + j] = s;
    }
}

// ---------------------------------------------------------------------------
extern "C" void kernel_launch(void* const* d_in, const int* in_sizes, int n_in,
                              void* d_out, int out_size) {
    const float* fm0   = (const float*)d_in[0];
    const float* fm1   = (const float*)d_in[1];
    const float* fm2   = (const float*)d_in[2];
    const float* fm3   = (const float*)d_in[3];
    const float* rois  = (const float*)d_in[4];
    const float* fc1_w = (const float*)d_in[5];
    const float* fc1_b = (const float*)d_in[6];
    const float* fc2_w = (const float*)d_in[7];
    const float* fc2_b = (const float*)d_in[8];
    const float* p_w   = (const float*)d_in[9];
    const float* p_b   = (const float*)d_in[10];
    float* out = (float*)d_out;

    int nrois = in_sizes[4] / 5;   // 1024
    int nj = out_size / nrois;     // 20

    static cudaStream_t s2 = nullptr;
    static cudaEvent_t evF = nullptr, evJ = nullptr;
    if (!s2) {
        cudaStreamCreateWithFlags(&s2, cudaStreamNonBlocking);
        cudaEventCreateWithFlags(&evF, cudaEventDisableTiming);
        cudaEventCreateWithFlags(&evJ, cudaEventDisableTiming);
    }

    __nv_bfloat16 *w1h, *w1l, *w2h, *w2l, *p5h, *p5l, *f1h, *f1l;
    float *fc2p, *partp;
    cudaGetSymbolAddress((void**)&w1h, g_w1_hi);
    cudaGetSymbolAddress((void**)&w1l, g_w1_lo);
    cudaGetSymbolAddress((void**)&w2h, g_w2_hi);
    cudaGetSymbolAddress((void**)&w2l, g_w2_lo);
    cudaGetSymbolAddress((void**)&p5h, g_p5_hi);
    cudaGetSymbolAddress((void**)&p5l, g_p5_lo);
    cudaGetSymbolAddress((void**)&f1h, g_fc1_hi);
    cudaGetSymbolAddress((void**)&f1l, g_fc1_lo);
    cudaGetSymbolAddress((void**)&fc2p, g_fc2);
    cudaGetSymbolAddress((void**)&partp, g_part);

    // Fork: weight splits run concurrent with transposes + ROI.
    cudaEventRecord(evF, 0);
    cudaStreamWaitEvent(s2, evF, 0);
    split_kernel<<<(12544 * 1024 / 4 + 255) / 256, 256, 0, s2>>>(fc1_w, w1h, w1l, 12544 * 1024 / 4);
    split_kernel<<<(1024 * 1024 / 4 + 255) / 256, 256, 0, s2>>>(fc2_w, w2h, w2l, 1024 * 1024 / 4);
    cudaEventRecord(evJ, s2);

    // Main: NCHW fp32 -> NHWC fp16, then ROIAlign.
    nchw2nhwc_kernel<<<dim3((61440 / 32 + 7) / 8, 8, 2), 256>>>(fm0, 61440, (size_t)0);
    nchw2nhwc_kernel<<<dim3((15360 / 32 + 7) / 8, 8, 2), 256>>>(fm1, 15360, (size_t)31457280);
    nchw2nhwc_kernel<<<dim3((3840 / 32 + 7) / 8, 8, 2), 256>>>(fm2, 3840, (size_t)39321600);
    nchw2nhwc_kernel<<<dim3((960 / 32 + 7) / 8, 8, 2), 256>>>(fm3, 960, (size_t)41287680);

    cudaFuncSetAttribute(roi_align_kernel,
                         cudaFuncAttributeMaxDynamicSharedMemorySize, 50176);
    roi_align_kernel<<<nrois, 256, 50176>>>(rois);

    cudaStreamWaitEvent(0, evJ, 0);

    const int GEMM_SMEM = 1024 + 3 * 65536;  // 197632 (3-stage)
    cudaFuncSetAttribute(gemm_tc<0>,
                         cudaFuncAttributeMaxDynamicSharedMemorySize, GEMM_SMEM);
    cudaFuncSetAttribute(gemm_tc<2>,
                         cudaFuncAttributeMaxDynamicSharedMemorySize, GEMM_SMEM);

    // FC1 split-K2: partials then reduce(+bias+relu+split).
    gemm_tc<2><<<dim3(8, nrois / 128, 2), 256, GEMM_SMEM>>>(
        p5h, p5l, w1h, w1l, nullptr, partp, 1024, 6272, 12544);
    reduce_split_kernel<<<1024, 256>>>(partp, fc1_b, f1h, f1l);

    // FC2: [1024, 1024] x [1024, 1024]^T -> fc2 fp32 (+bias+relu)
    gemm_tc<0><<<dim3(8, nrois / 128, 1), 256, GEMM_SMEM>>>(
        f1h, f1l, w2h, w2l, fc2_b, fc2p, 1024, 1024, 1024);

    // Projection
    proj_kernel<<<nrois, 256>>>(fc2p, p_w, p_b, out, nj);
}

// round 10
// speedup vs baseline: 1.6136x; 1.0522x over previous
#include <cuda_runtime.h>
#include <cuda_bf16.h>
#include <cuda_fp16.h>
#include <cstdint>

// ---------------------------------------------------------------------------
// Shapes: B=2, C=256, Im 768x1280, strides {4,8,16,32}, N=1024 rois
// pool5 D = 256*49 = 12544; fc1: 12544->1024 relu; fc2: 1024->1024 relu; proj->20
// ---------------------------------------------------------------------------

#define NCH 256

#if defined(__CUDA_ARCH__) && defined(__CUDA_ARCH_FEAT_SM103_ALL)
#define HAS_TCGEN05 1
#else
#define HAS_TCGEN05 0
#endif

__device__ __half g_nhwc[41779200];          // fp16 NHWC staging
__device__ __nv_bfloat16 g_p5_hi[1024 * 12544];
__device__ __nv_bfloat16 g_p5_lo[1024 * 12544];
__device__ __nv_bfloat16 g_w1_hi[1024 * 12544];
__device__ __nv_bfloat16 g_w1_lo[1024 * 12544];
__device__ __nv_bfloat16 g_fc1_hi[1024 * 1024];
__device__ __nv_bfloat16 g_fc1_lo[1024 * 1024];
__device__ __nv_bfloat16 g_w2_hi[1024 * 1024];
__device__ __nv_bfloat16 g_w2_lo[1024 * 1024];
__device__ float g_fc2[1024 * 1024];
__device__ float g_part[2 * 1024 * 1024];    // split-K partials (FC1, then FC2)

__constant__ size_t c_lvl_off[4] = {0, 31457280, 39321600, 41287680};

// ============================ PTX helpers ==================================
__device__ __forceinline__ uint32_t smem_u32(const void* p) {
    uint32_t a;
    asm("{ .reg .u64 t; cvta.to.shared.u64 t, %1; cvt.u32.u64 %0, t; }" : "=r"(a) : "l"(p));
    return a;
}
__device__ __forceinline__ uint32_t elect_one() {
    uint32_t p;
    asm volatile("{\n\t.reg .pred p;\n\telect.sync _|p, 0xFFFFFFFF;\n\tselp.b32 %0, 1, 0, p;\n\t}" : "=r"(p));
    return p;
}
#define MBARRIER_INIT(addr, cnt) \
    asm volatile("mbarrier.init.shared.b64 [%0], %1;" :: "r"(addr), "r"(cnt) : "memory")
#define MBARRIER_WAIT_PARITY(addr, par) do {                                          \
    uint32_t _m = (addr); uint32_t _p = (par); uint32_t _d;                           \
    asm volatile("{\n\t.reg .pred p;\n\t"                                             \
        "mbarrier.try_wait.parity.acquire.cta.shared::cta.b64 p, [%1], %2;\n\t"       \
        "selp.b32 %0, 1, 0, p;\n\t}" : "=r"(_d) : "r"(_m), "r"(_p) : "memory");       \
    if (!_d) {                                                                        \
        asm volatile("{\n\t.reg .pred P1;\n\t"                                        \
            "WL_%=:\n\t"                                                              \
            "mbarrier.try_wait.parity.acquire.cta.shared::cta.b64 P1, [%0], %1, 0x989680;\n\t" \
            "@P1 bra.uni WD_%=;\n\tbra.uni WL_%=;\n\tWD_%=:\n\t}"                     \
            :: "r"(_m), "r"(_p) : "memory");                                          \
    } } while (0)
#define FENCE_PROXY_ASYNC() asm volatile("fence.proxy.async.shared::cta;" ::: "memory")
#define CP_COMMIT() asm volatile("cp.async.commit_group;" ::: "memory")
#define CP_WAIT_1() asm volatile("cp.async.wait_group 1;" ::: "memory")

#if HAS_TCGEN05
#define TCGEN05_ALLOC(sa, n) \
    asm volatile("tcgen05.alloc.cta_group::1.sync.aligned.shared::cta.b32 [%0], %1;" :: "r"(sa), "r"(n) : "memory")
#define TCGEN05_DEALLOC(t, n) \
    asm volatile("tcgen05.dealloc.cta_group::1.sync.aligned.b32 %0, %1;" :: "r"(t), "r"(n))
#define TCGEN05_RELINQ() \
    asm volatile("tcgen05.relinquish_alloc_permit.cta_group::1.sync.aligned;")
#define TCGEN05_COMMIT(mb) \
    asm volatile("tcgen05.commit.cta_group::1.mbarrier::arrive::one.shared::cluster.b64 [%0];" :: "r"(mb) : "memory")
#define TCGEN05_FENCE_AFTER()  asm volatile("tcgen05.fence::after_thread_sync;" ::: "memory")
#define TCGEN05_FENCE_BEFORE() asm volatile("tcgen05.fence::before_thread_sync;" ::: "memory")
#define TCGEN05_WAIT_LD() asm volatile("tcgen05.wait::ld.sync.aligned;" ::: "memory")

#define TCGEN05_LD_X32(r, ta)                                                          \
    asm volatile("tcgen05.ld.sync.aligned.32x32b.x32.b32 "                             \
        "{%0, %1, %2, %3, %4, %5, %6, %7, %8, %9, %10, %11, %12, %13, %14, %15, "      \
        " %16, %17, %18, %19, %20, %21, %22, %23, %24, %25, %26, %27, %28, %29, %30, %31}, [%32];" \
        : "=r"((r)[0]), "=r"((r)[1]), "=r"((r)[2]), "=r"((r)[3]),                      \
          "=r"((r)[4]), "=r"((r)[5]), "=r"((r)[6]), "=r"((r)[7]),                      \
          "=r"((r)[8]), "=r"((r)[9]), "=r"((r)[10]), "=r"((r)[11]),                    \
          "=r"((r)[12]), "=r"((r)[13]), "=r"((r)[14]), "=r"((r)[15]),                  \
          "=r"((r)[16]), "=r"((r)[17]), "=r"((r)[18]), "=r"((r)[19]),                  \
          "=r"((r)[20]), "=r"((r)[21]), "=r"((r)[22]), "=r"((r)[23]),                  \
          "=r"((r)[24]), "=r"((r)[25]), "=r"((r)[26]), "=r"((r)[27]),                  \
          "=r"((r)[28]), "=r"((r)[29]), "=r"((r)[30]), "=r"((r)[31])                   \
        : "r"(ta))

__device__ __forceinline__ void mma_f16_ss(uint32_t d, uint64_t a, uint64_t b,
                                           uint32_t idesc, bool en) {
    uint32_t e = en ? 1u : 0u;
    asm volatile(
        "{\n\t.reg .pred p;\n\tsetp.ne.u32 p, %4, 0;\n\t"
        "tcgen05.mma.cta_group::1.kind::f16 [%0], %1, %2, %3, {%5, %5, %5, %5}, p;\n\t}"
        :: "r"(d), "l"(a), "l"(b), "r"(idesc), "r"(e), "r"(0u) : "memory");
}
#endif  // HAS_TCGEN05

// SW128 K-major descriptor: layout=2, version=1, SBO=64, LBO=1
static constexpr uint64_t DESC_BASE_SW128 =
    (uint64_t(2) << 61) | (uint64_t(1) << 46) | (uint64_t(64) << 32) | (uint64_t(1) << 16);
#define MAKE_DESC(a) (DESC_BASE_SW128 | ((uint64_t)((a) >> 4) & 0x3FFF))

// idesc kind::f16: F32 accum, BF16 a/b, M=128, N=128
static constexpr uint32_t GEMM_IDESC =
    (1u << 4) | (1u << 7) | (1u << 10) | ((128u / 8u) << 17) | ((128u / 16u) << 24);

__device__ __forceinline__ void pack_hi_lo(float v0, float v1, uint32_t& h, uint32_t& l) {
    asm("cvt.rn.bf16x2.f32 %0, %1, %2;" : "=r"(h) : "f"(v1), "f"(v0));
    float l0 = v0 - __uint_as_float(h << 16);
    float l1 = v1 - __uint_as_float(h & 0xffff0000u);
    asm("cvt.rn.bf16x2.f32 %0, %1, %2;" : "=r"(l) : "f"(l1), "f"(l0));
}

// ---------------------------------------------------------------------------
// All-level NCHW fp32 -> NHWC fp16 transpose in ONE launch.
// blockIdx.x in [0,319) maps to a level + local tile group:
//   fm0: 240 groups, fm1: 60, fm2: 15, fm3: 4. 8 tiles (32C x 32HW)/block.
// ---------------------------------------------------------------------------
__global__ void nchw2nhwc_all_kernel(const float* __restrict__ fm0,
                                     const float* __restrict__ fm1,
                                     const float* __restrict__ fm2,
                                     const float* __restrict__ fm3) {
    __shared__ float tile[8][32][33];
    int bx = blockIdx.x;
    int lvl, bl;
    if      (bx < 240) { lvl = 0; bl = bx; }
    else if (bx < 300) { lvl = 1; bl = bx - 240; }
    else if (bx < 315) { lvl = 2; bl = bx - 300; }
    else               { lvl = 3; bl = bx - 315; }
    int HW = 61440 >> (2 * lvl);
    const float* in = (lvl == 0) ? fm0 : (lvl == 1) ? fm1 : (lvl == 2) ? fm2 : fm3;
    size_t off = c_lvl_off[lvl];

    int b = blockIdx.z;
    int c0 = blockIdx.y * 32;
    int t = threadIdx.x;            // 256
    int cr  = t >> 3;               // 0..31
    int f4  = t & 7;                // 0..7

    int hwbase = bl * 256;
    int nrep = (HW - hwbase + 31) >> 5;      // uniform; 1..8
    if (nrep > 8) nrep = 8;

    float4 v[8];
#pragma unroll
    for (int rep = 0; rep < 8; rep++)
        if (rep < nrep)
            v[rep] = *((const float4*)(in + ((size_t)b * NCH + c0 + cr) * HW + hwbase + rep * 32) + f4);

#pragma unroll
    for (int rep = 0; rep < 8; rep++)
        if (rep < nrep) {
            tile[rep][f4 * 4 + 0][cr] = v[rep].x;
            tile[rep][f4 * 4 + 1][cr] = v[rep].y;
            tile[rep][f4 * 4 + 2][cr] = v[rep].z;
            tile[rep][f4 * 4 + 3][cr] = v[rep].w;
        }
    __syncthreads();

#pragma unroll
    for (int rep = 0; rep < 8; rep++)
        if (rep < nrep) {
            half2 a = __floats2half2_rn(tile[rep][cr][f4 * 4 + 0], tile[rep][cr][f4 * 4 + 1]);
            half2 c = __floats2half2_rn(tile[rep][cr][f4 * 4 + 2], tile[rep][cr][f4 * 4 + 3]);
            uint2 o;
            o.x = *(uint32_t*)&a;
            o.y = *(uint32_t*)&c;
            *(uint2*)(g_nhwc + off + ((size_t)b * HW + hwbase + rep * 32 + cr) * NCH + c0 + f4 * 4) = o;
        }
}

// ---------------------------------------------------------------------------
// ROIAlign from fp16 NHWC: 32 channel-octets x 8 bin-groups, fp32 math.
// ---------------------------------------------------------------------------
__device__ __forceinline__ void acc8(float* acc, uint4 v, float w) {
    half2* h = (half2*)&v;
#pragma unroll
    for (int e = 0; e < 4; e++) {
        float2 f = __half22float2(h[e]);
        acc[2 * e]     += w * f.x;
        acc[2 * e + 1] += w * f.y;
    }
}

__global__ void roi_align_kernel(const float* __restrict__ rois) {
    extern __shared__ float shbuf[];  // 12544 floats, [channel*49 + bin]
    __shared__ int   s_ix0[14], s_ix1[14], s_iy0[14], s_iy1[14];
    __shared__ float s_wx0[14], s_wx1[14], s_wy0[14], s_wy1[14];

    int n = blockIdx.x;
    int tid = threadIdx.x;
    int c8  = tid & 31;   // channel octet 0..31
    int grp = tid >> 5;   // 0..7

    const float* r = rois + (size_t)n * 5;
    int   b  = (int)r[0];
    float x1 = r[1], y1 = r[2], x2 = r[3], y2 = r[4];

    float w = x2 - x1, h = y2 - y1;
    float kf = floorf(4.0f + log2f(sqrtf(fmaxf(w * h, 1e-6f)) / 224.0f));
    kf = fminf(fmaxf(kf, 2.0f), 5.0f);
    int lvl = (int)kf - 2;

    float stride = (float)(4 << lvl);
    int H = 768 >> (lvl + 2);
    int W = 1280 >> (lvl + 2);
    const uint4* base4 = (const uint4*)(g_nhwc + c_lvl_off[lvl] + (size_t)b * H * W * NCH);

    if (tid < 28) {
        bool isx = tid < 14;
        int  s   = isx ? tid : tid - 14;
        float lo = isx ? x1 : y1;
        float hi = isx ? x2 : y2;
        int size = isx ? W : H;
        float a = lo / stride - 0.5f;
        float bb = hi / stride - 0.5f;
        float coord = a + (bb - a) * (((float)s + 0.5f) / 14.0f);
        float valid = (coord > -1.0f && coord < (float)size) ? 1.0f : 0.0f;
        float cc = fminf(fmaxf(coord, 0.0f), (float)(size - 1));
        int i0 = (int)floorf(cc);
        int i1 = min(i0 + 1, size - 1);
        float frac = cc - (float)i0;
        if (isx) { s_ix0[s] = i0; s_ix1[s] = i1; s_wx0[s] = (1.0f - frac) * valid; s_wx1[s] = frac * valid; }
        else     { s_iy0[s] = i0; s_iy1[s] = i1; s_wy0[s] = (1.0f - frac) * valid; s_wy1[s] = frac * valid; }
    }
    __syncthreads();

    for (int bin = grp; bin < 49; bin += 8) {
        int by = bin / 7, bx = bin - by * 7;
        float acc[8] = {};
#pragma unroll
        for (int i = 0; i < 2; i++) {
            int sy = by * 2 + i;
            float wy0 = s_wy0[sy], wy1 = s_wy1[sy];
            int row0 = s_iy0[sy] * W;
            int row1 = s_iy1[sy] * W;
#pragma unroll
            for (int j = 0; j < 2; j++) {
                int sx = bx * 2 + j;
                float wx0 = s_wx0[sx], wx1 = s_wx1[sx];
                int xa = s_ix0[sx], xb = s_ix1[sx];
                uint4 v00 = __ldg(base4 + (size_t)(row0 + xa) * 32 + c8);
                uint4 v01 = __ldg(base4 + (size_t)(row0 + xb) * 32 + c8);
                uint4 v10 = __ldg(base4 + (size_t)(row1 + xa) * 32 + c8);
                uint4 v11 = __ldg(base4 + (size_t)(row1 + xb) * 32 + c8);
                acc8(acc, v00, wy0 * wx0);
                acc8(acc, v01, wy0 * wx1);
                acc8(acc, v10, wy1 * wx0);
                acc8(acc, v11, wy1 * wx1);
            }
        }
        int ch = c8 * 8;
#pragma unroll
        for (int e = 0; e < 8; e++)
            shbuf[(ch + e) * 49 + bin] = acc[e] * 0.25f;
    }
    __syncthreads();

    uint32_t* hd = (uint32_t*)(g_p5_hi + (size_t)n * 12544);
    uint32_t* ld = (uint32_t*)(g_p5_lo + (size_t)n * 12544);
    for (int i = tid; i < 6272; i += 256) {
        float v0 = shbuf[2 * i], v1 = shbuf[2 * i + 1];
        uint32_t hh, ll;
        pack_hi_lo(v0, v1, hh, ll);
        hd[i] = hh; ld[i] = ll;
    }
}

// ---------------------------------------------------------------------------
// fp32 -> bf16 hi/lo split (for weights)
// ---------------------------------------------------------------------------
__global__ void split_kernel(const float* __restrict__ in,
                             __nv_bfloat16* __restrict__ hi,
                             __nv_bfloat16* __restrict__ lo, int n4) {
    int i = blockIdx.x * blockDim.x + threadIdx.x;
    if (i >= n4) return;
    float4 v = ((const float4*)in)[i];
    uint32_t h0, h1, l0, l1;
    pack_hi_lo(v.x, v.y, h0, l0);
    pack_hi_lo(v.z, v.w, h1, l1);
    ((uint2*)hi)[i] = make_uint2(h0, h1);
    ((uint2*)lo)[i] = make_uint2(l0, l1);
}

// ---------------------------------------------------------------------------
// Split-K reduces: relu(p0 + p1 + bias).
// Variant A -> bf16 hi/lo (FC1 activations). Variant B -> fp32 (FC2 out).
// ---------------------------------------------------------------------------
__global__ void reduce_split_kernel(const float* __restrict__ part,
                                    const float* __restrict__ bias,
                                    __nv_bfloat16* __restrict__ hi,
                                    __nv_bfloat16* __restrict__ lo) {
    int i = blockIdx.x * 256 + threadIdx.x;   // float4 index, 262144 total
    float4 a = ((const float4*)part)[i];
    float4 b = ((const float4*)(part + 1048576))[i];
    float4 bs = ((const float4*)bias)[i & 255];
    float v0 = fmaxf(a.x + b.x + bs.x, 0.0f);
    float v1 = fmaxf(a.y + b.y + bs.y, 0.0f);
    float v2 = fmaxf(a.z + b.z + bs.z, 0.0f);
    float v3 = fmaxf(a.w + b.w + bs.w, 0.0f);
    uint32_t h0, h1, l0, l1;
    pack_hi_lo(v0, v1, h0, l0);
    pack_hi_lo(v2, v3, h1, l1);
    ((uint2*)hi)[i] = make_uint2(h0, h1);
    ((uint2*)lo)[i] = make_uint2(l0, l1);
}

__global__ void reduce_fc2_kernel(const float* __restrict__ part,
                                  const float* __restrict__ bias,
                                  float* __restrict__ outf) {
    int i = blockIdx.x * 256 + threadIdx.x;
    float4 a = ((const float4*)part)[i];
    float4 b = ((const float4*)(part + 1048576))[i];
    float4 bs = ((const float4*)bias)[i & 255];
    float4 o;
    o.x = fmaxf(a.x + b.x + bs.x, 0.0f);
    o.y = fmaxf(a.y + b.y + bs.y, 0.0f);
    o.z = fmaxf(a.z + b.z + bs.z, 0.0f);
    o.w = fmaxf(a.w + b.w + bs.w, 0.0f);
    ((float4*)outf)[i] = o;
}

// ---------------------------------------------------------------------------
// GEMM: C[M,N] = A[M,K] @ B[N,K]^T, tcgen05 hi/lo bf16, 128x128 tile, BK=64,
// 3-stage cp.async pipeline. blockIdx.z = split-K slice.
// Raw fp32 out (all uses are split-K partials now).
// ---------------------------------------------------------------------------
__device__ __forceinline__ void load_tile16(uint32_t s_tile, const __nv_bfloat16* g,
                                            int ldK, int tid) {
#pragma unroll
    for (int q = 0; q < 4; q++) {
        int gid = tid + q * 256;
        int row = gid >> 3, c16 = gid & 7;
        uint32_t dst = s_tile + row * 128 + ((c16 ^ (row & 7)) << 4);
        const char* src = (const char*)(g + (size_t)row * ldK) + (c16 << 4);
        asm volatile("cp.async.cg.shared.global [%0], [%1], 16;" :: "r"(dst), "l"(src) : "memory");
    }
}

__global__ __launch_bounds__(256, 1) void gemm_tc(
    const __nv_bfloat16* __restrict__ Ahi, const __nv_bfloat16* __restrict__ Alo,
    const __nv_bfloat16* __restrict__ Bhi, const __nv_bfloat16* __restrict__ Blo,
    float* __restrict__ Cf,
    int N, int K, int ldK) {
    extern __shared__ char dsm[];
    int tid = threadIdx.x;
    int bm = blockIdx.y * 128, bn = blockIdx.x * 128;
    int z = blockIdx.z;
    size_t koff = (size_t)z * K;

    const __nv_bfloat16* Ah = Ahi + (size_t)bm * ldK + koff;
    const __nv_bfloat16* Al = Alo + (size_t)bm * ldK + koff;
    const __nv_bfloat16* Bh = Bhi + (size_t)bn * ldK + koff;
    const __nv_bfloat16* Bl = Blo + (size_t)bn * ldK + koff;
    float* Cz = Cf + (size_t)z * (size_t)(gridDim.y * 128) * N;

#if HAS_TCGEN05
    __shared__ uint32_t s_tmem;
    __shared__ uint64_t s_mbar[3];

    uint32_t sbase = (smem_u32(dsm) + 1023u) & ~1023u;
    int wid = tid >> 5, lid = tid & 31;

    uint32_t mb[3] = { smem_u32(&s_mbar[0]), smem_u32(&s_mbar[1]), smem_u32(&s_mbar[2]) };

    if (wid == 0) TCGEN05_ALLOC(smem_u32(&s_tmem), 128);
    if (tid == 0) { MBARRIER_INIT(mb[0], 1); MBARRIER_INIT(mb[1], 1); MBARRIER_INIT(mb[2], 1); }
    __syncthreads();
    uint32_t tmem = s_tmem;
    if (wid == 0) TCGEN05_RELINQ();

    const int nblk = K >> 6;

#pragma unroll
    for (int p = 0; p < 2; p++) {
        uint32_t st = sbase + (uint32_t)p * 65536u;
        load_tile16(st,          Ah + p * 64, ldK, tid);
        load_tile16(st + 16384u, Al + p * 64, ldK, tid);
        load_tile16(st + 32768u, Bh + p * 64, ldK, tid);
        load_tile16(st + 49152u, Bl + p * 64, ldK, tid);
        CP_COMMIT();
    }

    int ph[3] = {0, 0, 0};
    int s = 0, sp = 2;
    for (int i = 0; i < nblk; i++) {
        CP_WAIT_1();
        __syncthreads();
        if (tid < 32) {
            if (elect_one()) {
                FENCE_PROXY_ASYNC();
                uint32_t st = sbase + (uint32_t)s * 65536u;
                uint64_t dah = MAKE_DESC(st);
                uint64_t dal = MAKE_DESC(st + 16384u);
                uint64_t dbh = MAKE_DESC(st + 32768u);
                uint64_t dbl = MAKE_DESC(st + 49152u);
                bool en = (i > 0);
#pragma unroll
                for (int k = 0; k < 4; k++) {
                    mma_f16_ss(tmem, dah + k * 2, dbh + k * 2, GEMM_IDESC, en); en = true;
                    mma_f16_ss(tmem, dah + k * 2, dbl + k * 2, GEMM_IDESC, true);
                    mma_f16_ss(tmem, dal + k * 2, dbh + k * 2, GEMM_IDESC, true);
                }
                TCGEN05_COMMIT(mb[s]);
            }
        }
        if (i >= 1) {
            MBARRIER_WAIT_PARITY(mb[sp], ph[sp]);
            ph[sp] ^= 1;
            if (i + 2 < nblk) {
                uint32_t st = sbase + (uint32_t)sp * 65536u;
                int j = i + 2;
                load_tile16(st,          Ah + j * 64, ldK, tid);
                load_tile16(st + 16384u, Al + j * 64, ldK, tid);
                load_tile16(st + 32768u, Bh + j * 64, ldK, tid);
                load_tile16(st + 49152u, Bl + j * 64, ldK, tid);
            }
        } else if (nblk > 2) {
            uint32_t st = sbase + 2u * 65536u;
            load_tile16(st,          Ah + 2 * 64, ldK, tid);
            load_tile16(st + 16384u, Al + 2 * 64, ldK, tid);
            load_tile16(st + 32768u, Bh + 2 * 64, ldK, tid);
            load_tile16(st + 49152u, Bl + 2 * 64, ldK, tid);
        }
        CP_COMMIT();
        sp = s;
        s = (s == 2) ? 0 : s + 1;
    }

    {
        int lastS = (nblk - 1) % 3;
        MBARRIER_WAIT_PARITY(mb[lastS], ph[lastS]);
    }
    TCGEN05_FENCE_AFTER();

    if (tid < 128) {
        int row = bm + wid * 32 + lid;
#pragma unroll
        for (int cb = 0; cb < 128; cb += 32) {
            uint32_t rr[32];
            TCGEN05_LD_X32(rr, tmem + cb);
            TCGEN05_WAIT_LD();
            float* cd = Cz + (size_t)row * N + bn + cb;
#pragma unroll
            for (int c = 0; c < 32; c++)
                cd[c] = __uint_as_float(rr[c]);
        }
        TCGEN05_FENCE_BEFORE();
    }
    __syncthreads();
    if (wid == 0) TCGEN05_DEALLOC(tmem, 128);

#else  // ---------------- SIMT fallback (baseline compute_103 pass) ---------
    float* As = (float*)dsm;
    float* Bs = As + 16 * 132;

    int tr = (tid >> 4) * 8;
    int tc = (tid & 15) * 8;

    float acc[8][8] = {};

    for (int k0 = 0; k0 < K; k0 += 16) {
#pragma unroll
        for (int e = 0; e < 8; e++) {
            int idx = tid * 8 + e;
            int kk = idx >> 7, rr = idx & 127;
            As[kk * 132 + rr] = __bfloat162float(Ah[(size_t)rr * ldK + k0 + kk]) +
                                __bfloat162float(Al[(size_t)rr * ldK + k0 + kk]);
            Bs[kk * 132 + rr] = __bfloat162float(Bh[(size_t)rr * ldK + k0 + kk]) +
                                __bfloat162float(Bl[(size_t)rr * ldK + k0 + kk]);
        }
        __syncthreads();
#pragma unroll
        for (int k = 0; k < 16; k++) {
            float ra[8], rb[8];
#pragma unroll
            for (int i = 0; i < 8; i++) ra[i] = As[k * 132 + tr + i];
#pragma unroll
            for (int j = 0; j < 8; j++) rb[j] = Bs[k * 132 + tc + j];
#pragma unroll
            for (int i = 0; i < 8; i++)
#pragma unroll
                for (int j = 0; j < 8; j++) acc[i][j] += ra[i] * rb[j];
        }
        __syncthreads();
    }

#pragma unroll
    for (int i = 0; i < 8; i++)
#pragma unroll
        for (int j = 0; j < 8; j++)
            Cz[(size_t)(bm + tr + i) * N + bn + tc + j] = acc[i][j];
#endif
}

// ---------------------------------------------------------------------------
// Projection: out[n, j] = dot(fc2[n,:], p_w[j,:]) + p_b[j], j < 20.
// 128 threads: (j, kchunk) pairs, 256-elem partial dots + smem reduce.
// ---------------------------------------------------------------------------
__global__ void proj_kernel(const float* __restrict__ fc2,
                            const float* __restrict__ p_w,
                            const float* __restrict__ p_b,
                            float* __restrict__ out, int NJ) {
    __shared__ float sh[1024];
    __shared__ float red[32][4];
    int n = blockIdx.x;
    int t = threadIdx.x;   // 128
    for (int i = t; i < 1024; i += 128)
        sh[i] = fc2[(size_t)n * 1024 + i];
    __syncthreads();
    int j = t >> 2, ck = t & 3;
    if (j < NJ) {
        const float* wrow = p_w + (size_t)j * 1024 + ck * 256;
        const float* sv = sh + ck * 256;
        float s = 0.0f;
#pragma unroll 8
        for (int k = 0; k < 256; k++) s += sv[k] * wrow[k];
        red[j][ck] = s;
    }
    __syncthreads();
    if (t < NJ)
        out[(size_t)n * NJ + t] = red[t][0] + red[t][1] + red[t][2] + red[t][3] + p_b[t];
}

// ---------------------------------------------------------------------------
extern "C" void kernel_launch(void* const* d_in, const int* in_sizes, int n_in,
                              void* d_out, int out_size) {
    const float* fm0   = (const float*)d_in[0];
    const float* fm1   = (const float*)d_in[1];
    const float* fm2   = (const float*)d_in[2];
    const float* fm3   = (const float*)d_in[3];
    const float* rois  = (const float*)d_in[4];
    const float* fc1_w = (const float*)d_in[5];
    const float* fc1_b = (const float*)d_in[6];
    const float* fc2_w = (const float*)d_in[7];
    const float* fc2_b = (const float*)d_in[8];
    const float* p_w   = (const float*)d_in[9];
    const float* p_b   = (const float*)d_in[10];
    float* out = (float*)d_out;

    int nrois = in_sizes[4] / 5;   // 1024
    int nj = out_size / nrois;     // 20

    static cudaStream_t s2 = nullptr;
    static cudaEvent_t evF = nullptr, evJ = nullptr;
    if (!s2) {
        cudaStreamCreateWithFlags(&s2, cudaStreamNonBlocking);
        cudaEventCreateWithFlags(&evF, cudaEventDisableTiming);
        cudaEventCreateWithFlags(&evJ, cudaEventDisableTiming);
    }

    __nv_bfloat16 *w1h, *w1l, *w2h, *w2l, *p5h, *p5l, *f1h, *f1l;
    float *fc2p, *partp;
    cudaGetSymbolAddress((void**)&w1h, g_w1_hi);
    cudaGetSymbolAddress((void**)&w1l, g_w1_lo);
    cudaGetSymbolAddress((void**)&w2h, g_w2_hi);
    cudaGetSymbolAddress((void**)&w2l, g_w2_lo);
    cudaGetSymbolAddress((void**)&p5h, g_p5_hi);
    cudaGetSymbolAddress((void**)&p5l, g_p5_lo);
    cudaGetSymbolAddress((void**)&f1h, g_fc1_hi);
    cudaGetSymbolAddress((void**)&f1l, g_fc1_lo);
    cudaGetSymbolAddress((void**)&fc2p, g_fc2);
    cudaGetSymbolAddress((void**)&partp, g_part);

    // Fork: weight splits run concurrent with transpose + ROI.
    cudaEventRecord(evF, 0);
    cudaStreamWaitEvent(s2, evF, 0);
    split_kernel<<<(12544 * 1024 / 4 + 255) / 256, 256, 0, s2>>>(fc1_w, w1h, w1l, 12544 * 1024 / 4);
    split_kernel<<<(1024 * 1024 / 4 + 255) / 256, 256, 0, s2>>>(fc2_w, w2h, w2l, 1024 * 1024 / 4);
    cudaEventRecord(evJ, s2);

    // Main: all-level NCHW fp32 -> NHWC fp16 in one launch, then ROIAlign.
    nchw2nhwc_all_kernel<<<dim3(319, 8, 2), 256>>>(fm0, fm1, fm2, fm3);

    cudaFuncSetAttribute(roi_align_kernel,
                         cudaFuncAttributeMaxDynamicSharedMemorySize, 50176);
    roi_align_kernel<<<nrois, 256, 50176>>>(rois);

    cudaStreamWaitEvent(0, evJ, 0);

    const int GEMM_SMEM = 1024 + 3 * 65536;  // 197632 (3-stage)
    cudaFuncSetAttribute(gemm_tc,
                         cudaFuncAttributeMaxDynamicSharedMemorySize, GEMM_SMEM);

    // FC1 split-K2: partials then reduce(+bias+relu+split to bf16 hi/lo).
    gemm_tc<<<dim3(8, nrois / 128, 2), 256, GEMM_SMEM>>>(
        p5h, p5l, w1h, w1l, partp, 1024, 6272, 12544);
    reduce_split_kernel<<<1024, 256>>>(partp, fc1_b, f1h, f1l);

    // FC2 split-K2: partials then reduce(+bias+relu) to fp32.
    gemm_tc<<<dim3(8, nrois / 128, 2), 256, GEMM_SMEM>>>(
        f1h, f1l, w2h, w2l, partp, 1024, 512, 1024);
    reduce_fc2_kernel<<<1024, 256>>>(partp, fc2_b, fc2p);

    // Projection
    proj_kernel<<<nrois, 128>>>(fc2p, p_w, p_b, out, nj);
}